// round 6
// baseline (speedup 1.0000x reference)
#include <cuda_runtime.h>
#include <cuda_fp16.h>
#include <cstdint>
#include <cstddef>

#define T_ 2048
#define H_ 1024
#define F_ 512
#define E_ 32
#define K_ 4
#define NSLOT (T_*K_)
#define SLOTPAD (NSLOT+128)
#define MAXTILES 96

#define AST 40                         // smem row stride in halves
#define GU_STGH (128*AST + 2*64*AST)   // 10240 halves / stage
#define GU_SMEM (2*GU_STGH*2)          // 40960 B
#define GU_GOFF (128*AST)              // 5120
#define GU_UOFF (128*AST + 64*AST)     // 7680
#define DN_STGH (128*AST + 64*AST)     // 7680 halves
#define DN_SMEM (2*DN_STGH*2)          // 30720 B
#define DN_BOFF (128*AST)

// ---------------- scratch ----------------
__device__ int    g_cnt[E_];
__device__ int    g_pos[E_];
__device__ int    g_off[E_+1];
__device__ int    g_sel[NSLOT];
__device__ float  g_wgt[NSLOT];
__device__ int    g_slotTok[SLOTPAD];
__device__ float  g_slotW[SLOTPAD];
__device__ int    g_slotOf[NSLOT];
__device__ int    g_tileE[MAXTILES];
__device__ int    g_tileM[MAXTILES];
__device__ __half g_Hbuf16[(size_t)SLOTPAD*F_];
__device__ float  g_Ybuf[(size_t)SLOTPAD*H_];

// ---------------- helpers ----------------
__device__ __forceinline__ uint4 pack8(float4 a, float4 b){
    uint4 r;
    ((__half2*)&r)[0] = __floats2half2_rn(a.x, a.y);
    ((__half2*)&r)[1] = __floats2half2_rn(a.z, a.w);
    ((__half2*)&r)[2] = __floats2half2_rn(b.x, b.y);
    ((__half2*)&r)[3] = __floats2half2_rn(b.z, b.w);
    return r;
}
__device__ __forceinline__ void mma_f16(float* c, uint32_t a0,uint32_t a1,uint32_t a2,uint32_t a3,
                                        uint32_t b0,uint32_t b1){
    asm("mma.sync.aligned.m16n8k16.row.col.f32.f16.f16.f32 "
        "{%0,%1,%2,%3},{%4,%5,%6,%7},{%8,%9},{%0,%1,%2,%3};"
        : "+f"(c[0]),"+f"(c[1]),"+f"(c[2]),"+f"(c[3])
        : "r"(a0),"r"(a1),"r"(a2),"r"(a3),"r"(b0),"r"(b1));
}

// ---------------- 1. router (exact fp32, 2 tokens/warp) --------------------
__global__ __launch_bounds__(256) void router_kernel(const float* __restrict__ RI,
                                                     const float* __restrict__ WR,
                                                     float* __restrict__ logits){
    int gid = blockIdx.x*256 + threadIdx.x;
    if (blockIdx.x==0){
        if (threadIdx.x < E_) g_cnt[threadIdx.x] = 0;
        else if (threadIdx.x < 2*E_) g_pos[threadIdx.x-E_] = 0;
    }
    int warp = gid >> 5, lane = gid & 31;
    int t0 = warp*2;
    if (t0 >= T_) return;
    const float* xa = RI + (size_t)t0*H_;
    const float* xb = RI + (size_t)(t0+1)*H_;
    float4 ra[8], rb[8];
    #pragma unroll
    for (int j=0;j<8;j++){ ra[j] = *(const float4*)&xa[j*128 + lane*4];
                           rb[j] = *(const float4*)&xb[j*128 + lane*4]; }
    for (int e=0;e<E_;e++){
        const float* w = WR + (size_t)e*H_;
        float s0=0.f, s1=0.f;
        #pragma unroll
        for (int j=0;j<8;j++){
            float4 wv = *(const float4*)&w[j*128 + lane*4];
            s0 += ra[j].x*wv.x + ra[j].y*wv.y + ra[j].z*wv.z + ra[j].w*wv.w;
            s1 += rb[j].x*wv.x + rb[j].y*wv.y + rb[j].z*wv.z + rb[j].w*wv.w;
        }
        #pragma unroll
        for (int off=16;off;off>>=1){
            s0 += __shfl_xor_sync(0xffffffffu, s0, off);
            s1 += __shfl_xor_sync(0xffffffffu, s1, off);
        }
        if (lane==0){ logits[t0*E_+e] = s0; logits[(t0+1)*E_+e] = s1; }
    }
}

// ---------------- 2. top-4 + softmax + counts -------------------------------
__global__ __launch_bounds__(256) void topk_kernel(const float* __restrict__ logits){
    int t    = (blockIdx.x*256 + threadIdx.x) >> 5;
    int lane = threadIdx.x & 31;
    if (t >= T_) return;
    float cur = logits[t*E_ + lane];
    int   idx = lane;
    float vsel[K_]; int isel[K_];
    #pragma unroll
    for (int k=0;k<K_;k++){
        float bv = cur; int bi = idx;
        #pragma unroll
        for (int off=16;off;off>>=1){
            float ov = __shfl_xor_sync(0xffffffffu, bv, off);
            int   oi = __shfl_xor_sync(0xffffffffu, bi, off);
            if (ov > bv || (ov == bv && oi < bi)){ bv = ov; bi = oi; }
        }
        vsel[k]=bv; isel[k]=bi;
        if (idx == bi) cur = -__int_as_float(0x7f800000);
    }
    float mx = vsel[0], den = 0.f, w[K_];
    #pragma unroll
    for (int k=0;k<K_;k++){ w[k] = expf(vsel[k]-mx); den += w[k]; }
    if (lane < K_){
        g_sel[t*K_+lane] = isel[lane];
        g_wgt[t*K_+lane] = w[lane]/den;
        atomicAdd(&g_cnt[isel[lane]], 1);
    }
}

// ---------------- 3. scan + 128-row tile table ------------------------------
__global__ void scan_kernel(){
    if (threadIdx.x != 0) return;
    int acc = 0;
    for (int e=0;e<E_;e++){ g_off[e]=acc; acc += g_cnt[e]; }
    g_off[E_] = acc;
    int tt = 0;
    for (int e=0;e<E_;e++){
        int nt = (g_cnt[e]+127)>>7;
        for (int i=0;i<nt;i++){ g_tileE[tt]=e; g_tileM[tt]=i; tt++; }
    }
    for (; tt<MAXTILES; tt++) g_tileE[tt] = -1;
}

// ---------------- 4. scatter --------------------------------------------------
__global__ __launch_bounds__(256) void scatter_kernel(){
    int idx = blockIdx.x*256 + threadIdx.x;
    if (idx >= NSLOT) return;
    int e = g_sel[idx];
    int slot = g_off[e] + atomicAdd(&g_pos[e], 1);
    g_slotTok[slot] = idx >> 2;
    g_slotW[slot]   = g_wgt[idx];
    g_slotOf[idx]   = slot;
}

// ---------------- 5. gate+up GEMM: fp16 mma, 128x64 tile, 2-stage -----------
// A: thread t loads row t>>1, f32 cols (t&1)*16..+15 (4 float4)
// B: thread t loads row t>>2, f32 cols (t&3)*8..+7   (2 float4 each G,U)
__global__ __launch_bounds__(256) void gateup_f16(const float* __restrict__ X,
                                                  const float* __restrict__ WG,
                                                  const float* __restrict__ WU){
    extern __shared__ char smem[];
    int tile = blockIdx.y;
    int e = g_tileE[tile];
    if (e < 0) return;
    int n0 = blockIdx.x*64;
    int m0 = g_tileM[tile]*128;
    int base = g_off[e];
    int Me   = g_off[e+1] - base;
    int tid = threadIdx.x, lane = tid&31, wid = tid>>5;

    int rowA = tid>>1, cA = (tid&1)*16;
    int tokA = g_slotTok[base + m0 + rowA];
    const float* pA = X + (size_t)tokA*H_ + cA;
    int rowB = tid>>2, cB = (tid&3)*8;
    const float* pG = WG + (size_t)e*F_*H_ + (size_t)(n0+rowB)*H_ + cB;
    const float* pU = WU + (size_t)e*F_*H_ + (size_t)(n0+rowB)*H_ + cB;
    uint32_t dA = rowA*AST + cA;
    uint32_t dB = rowB*AST + cB;

    float4 a0,a1,a2,a3, gg0,gg1, uu0,uu1;
    a0=*(const float4*)(pA);    a1=*(const float4*)(pA+4);
    a2=*(const float4*)(pA+8);  a3=*(const float4*)(pA+12);
    gg0=*(const float4*)(pG);   gg1=*(const float4*)(pG+4);
    uu0=*(const float4*)(pU);   uu1=*(const float4*)(pU+4);

    int g = lane>>2, tg = lane&3;
    int wm = wid&3, wn = wid>>2;
    float accG[2][4][4] = {}; float accU[2][4][4] = {};

    const int NK = H_/32;
    for (int kt=0; kt<NK; kt++){
        int s = kt & 1;
        __half* st = (__half*)smem + s*GU_STGH;
        __syncthreads();
        *(uint4*)(st + dA)     = pack8(a0,a1);
        *(uint4*)(st + dA + 8) = pack8(a2,a3);
        *(uint4*)(st + GU_GOFF + dB) = pack8(gg0,gg1);
        *(uint4*)(st + GU_UOFF + dB) = pack8(uu0,uu1);
        __syncthreads();
        if (kt+1 < NK){
            int ko = (kt+1)*32;
            a0=*(const float4*)(pA+ko);    a1=*(const float4*)(pA+ko+4);
            a2=*(const float4*)(pA+ko+8);  a3=*(const float4*)(pA+ko+12);
            gg0=*(const float4*)(pG+ko);   gg1=*(const float4*)(pG+ko+4);
            uu0=*(const float4*)(pU+ko);   uu1=*(const float4*)(pU+ko+4);
        }
        const __half* A0 = st;
        const __half* G0 = st + GU_GOFF;
        const __half* U0 = st + GU_UOFF;
        #pragma unroll
        for (int ks=0; ks<2; ks++){
            int kb = ks*16 + 2*tg;
            uint32_t af[2][4];
            #pragma unroll
            for (int mt=0; mt<2; mt++){
                int r0 = wm*32 + mt*16 + g;
                af[mt][0] = *(const uint32_t*)(A0 + r0*AST     + kb);
                af[mt][1] = *(const uint32_t*)(A0 + (r0+8)*AST + kb);
                af[mt][2] = *(const uint32_t*)(A0 + r0*AST     + kb + 8);
                af[mt][3] = *(const uint32_t*)(A0 + (r0+8)*AST + kb + 8);
            }
            #pragma unroll
            for (int nf=0; nf<4; nf++){
                int nn = wn*32 + nf*8 + g;
                uint32_t bg0 = *(const uint32_t*)(G0 + nn*AST + kb);
                uint32_t bg1 = *(const uint32_t*)(G0 + nn*AST + kb + 8);
                uint32_t bu0 = *(const uint32_t*)(U0 + nn*AST + kb);
                uint32_t bu1 = *(const uint32_t*)(U0 + nn*AST + kb + 8);
                #pragma unroll
                for (int mt=0; mt<2; mt++){
                    mma_f16(accG[mt][nf], af[mt][0],af[mt][1],af[mt][2],af[mt][3], bg0,bg1);
                    mma_f16(accU[mt][nf], af[mt][0],af[mt][1],af[mt][2],af[mt][3], bu0,bu1);
                }
            }
        }
    }

    // epilogue: h = relu(gate)*up, fp16 store
    #pragma unroll
    for (int mt=0; mt<2; mt++){
        #pragma unroll
        for (int half=0; half<2; half++){
            int r = wm*32 + mt*16 + half*8 + g;
            if (m0 + r < Me){
                size_t ob = (size_t)(base+m0+r)*F_ + n0;
                #pragma unroll
                for (int nf=0; nf<4; nf++){
                    int col = wn*32 + nf*8 + 2*tg;
                    float h0 = fmaxf(accG[mt][nf][half*2  ],0.f)*accU[mt][nf][half*2  ];
                    float h1 = fmaxf(accG[mt][nf][half*2+1],0.f)*accU[mt][nf][half*2+1];
                    *(__half2*)&g_Hbuf16[ob + col] = __floats2half2_rn(h0,h1);
                }
            }
        }
    }
}

// ---------------- 6. down GEMM: fp16 mma, 128x64 tile, 2-stage --------------
__global__ __launch_bounds__(256) void down_f16(const float* __restrict__ WD){
    extern __shared__ char smem[];
    int tile = blockIdx.y;
    int e = g_tileE[tile];
    if (e < 0) return;
    int n0 = blockIdx.x*64;
    int m0 = g_tileM[tile]*128;
    int base = g_off[e];
    int Me   = g_off[e+1] - base;
    int tid = threadIdx.x, lane = tid&31, wid = tid>>5;

    int rowA = tid>>1, cA = (tid&1)*16;          // halves
    const __half* pA = g_Hbuf16 + (size_t)(base+m0+rowA)*F_ + cA;
    int rowB = tid>>2, cB = (tid&3)*8;           // f32
    const float* pB = WD + (size_t)e*H_*F_ + (size_t)(n0+rowB)*F_ + cB;
    uint32_t dA = rowA*AST + cA;
    uint32_t dB = rowB*AST + cB;

    uint4 qa0, qa1; float4 b0f, b1f;
    qa0 = *(const uint4*)(pA);
    qa1 = *(const uint4*)(pA + 8);
    b0f = *(const float4*)(pB);
    b1f = *(const float4*)(pB + 4);

    int g = lane>>2, tg = lane&3;
    int wm = wid&3, wn = wid>>2;
    float acc[2][4][4] = {};

    const int NK = F_/32;
    for (int kt=0; kt<NK; kt++){
        int s = kt & 1;
        __half* st = (__half*)smem + s*DN_STGH;
        __syncthreads();
        *(uint4*)(st + dA)     = qa0;
        *(uint4*)(st + dA + 8) = qa1;
        *(uint4*)(st + DN_BOFF + dB) = pack8(b0f,b1f);
        __syncthreads();
        if (kt+1 < NK){
            int ko = (kt+1)*32;
            qa0 = *(const uint4*)(pA + ko);
            qa1 = *(const uint4*)(pA + ko + 8);
            b0f = *(const float4*)(pB + ko);
            b1f = *(const float4*)(pB + ko + 4);
        }
        const __half* A0 = st;
        const __half* B0 = st + DN_BOFF;
        #pragma unroll
        for (int ks=0; ks<2; ks++){
            int kb = ks*16 + 2*tg;
            uint32_t af[2][4];
            #pragma unroll
            for (int mt=0; mt<2; mt++){
                int r0 = wm*32 + mt*16 + g;
                af[mt][0] = *(const uint32_t*)(A0 + r0*AST     + kb);
                af[mt][1] = *(const uint32_t*)(A0 + (r0+8)*AST + kb);
                af[mt][2] = *(const uint32_t*)(A0 + r0*AST     + kb + 8);
                af[mt][3] = *(const uint32_t*)(A0 + (r0+8)*AST + kb + 8);
            }
            #pragma unroll
            for (int nf=0; nf<4; nf++){
                int nn = wn*32 + nf*8 + g;
                uint32_t bb0 = *(const uint32_t*)(B0 + nn*AST + kb);
                uint32_t bb1 = *(const uint32_t*)(B0 + nn*AST + kb + 8);
                #pragma unroll
                for (int mt=0; mt<2; mt++)
                    mma_f16(acc[mt][nf], af[mt][0],af[mt][1],af[mt][2],af[mt][3], bb0,bb1);
            }
        }
    }

    #pragma unroll
    for (int mt=0; mt<2; mt++){
        #pragma unroll
        for (int half=0; half<2; half++){
            int r = wm*32 + mt*16 + half*8 + g;
            if (m0 + r < Me){
                float wsc = g_slotW[base+m0+r];
                size_t ob = (size_t)(base+m0+r)*H_ + n0;
                #pragma unroll
                for (int nf=0; nf<4; nf++){
                    int col = wn*32 + nf*8 + 2*tg;
                    float2 o;
                    o.x = acc[mt][nf][half*2  ]*wsc;
                    o.y = acc[mt][nf][half*2+1]*wsc;
                    *(float2*)&g_Ybuf[ob + col] = o;
                }
            }
        }
    }
}

// ---------------- 7. deterministic combine ----------------------------------
__global__ __launch_bounds__(256) void combine_kernel(float* __restrict__ out){
    int t = blockIdx.x;
    int h = threadIdx.x * 4;
    float4 acc = make_float4(0.f,0.f,0.f,0.f);
    #pragma unroll
    for (int k=0;k<K_;k++){
        int s = g_slotOf[t*K_+k];
        float4 v = *(const float4*)&g_Ybuf[(size_t)s*H_ + h];
        acc.x += v.x; acc.y += v.y; acc.z += v.z; acc.w += v.w;
    }
    *(float4*)&out[(size_t)t*H_ + h] = acc;
}

// ---------------- launch ----------------------------------------------------
extern "C" void kernel_launch(void* const* d_in, const int* in_sizes, int n_in,
                              void* d_out, int out_size){
    const float* RI = (const float*)d_in[0];
    const float* HS = (const float*)d_in[1];
    const float* WR = (const float*)d_in[2];
    const float* WG = (const float*)d_in[3];
    const float* WU = (const float*)d_in[4];
    const float* WD = (const float*)d_in[5];
    float* out    = (float*)d_out;
    float* logits = out + (size_t)T_*H_;

    cudaFuncSetAttribute(gateup_f16, cudaFuncAttributeMaxDynamicSharedMemorySize, GU_SMEM);
    cudaFuncSetAttribute(down_f16,   cudaFuncAttributeMaxDynamicSharedMemorySize, DN_SMEM);

    router_kernel <<<T_/16, 256>>>(RI, WR, logits);
    topk_kernel   <<<T_/8, 256>>>(logits);
    scan_kernel   <<<1, 32>>>();
    scatter_kernel<<<NSLOT/256, 256>>>();
    gateup_f16    <<<dim3(F_/64, MAXTILES), 256, GU_SMEM>>>(HS, WG, WU);
    down_f16      <<<dim3(H_/64, MAXTILES), 256, DN_SMEM>>>(WD);
    combine_kernel<<<T_, 256>>>(out);
}

// round 7
// speedup vs baseline: 1.6166x; 1.6166x over previous
#include <cuda_runtime.h>
#include <cuda_fp16.h>
#include <cstdint>
#include <cstddef>

#define T_ 2048
#define H_ 1024
#define F_ 512
#define E_ 32
#define K_ 4
#define NSLOT (T_*K_)
#define SLOTPAD (NSLOT+128)
#define MAXTILES 96

#define AST 48                 // smem row stride in halves (96B, 16B-aligned rows)
#define GU_STG_B  24576        // A 128*96 + G 64*96 + U 64*96
#define GU_GOFF_B 12288
#define GU_UOFF_B 18432
#define GU_SMEM   (3*GU_STG_B) // 73728
#define DN_STG_B  18432        // A 128*96 + B 64*96
#define DN_BOFF_B 12288
#define DN_SMEM   (3*DN_STG_B) // 55296

// ---------------- scratch ----------------
__device__ int    g_cnt[E_];
__device__ int    g_pos[E_];
__device__ int    g_off[E_+1];
__device__ int    g_sel[NSLOT];
__device__ float  g_wgt[NSLOT];
__device__ int    g_slotTok[SLOTPAD];
__device__ float  g_slotW[SLOTPAD];
__device__ int    g_slotOf[NSLOT];
__device__ int    g_tileE[MAXTILES];
__device__ int    g_tileM[MAXTILES];
__device__ __half g_WGh[(size_t)E_*F_*H_];
__device__ __half g_WUh[(size_t)E_*F_*H_];
__device__ __half g_WDh[(size_t)E_*H_*F_];
__device__ __half g_Xh [(size_t)T_*H_];
__device__ __half g_Hbuf16[(size_t)SLOTPAD*F_];
__device__ float  g_Ybuf[(size_t)SLOTPAD*H_];

// ---------------- helpers ----------------
__device__ __forceinline__ uint32_t smem_u32(const void* p){
    uint32_t a; asm("{ .reg .u64 t; cvta.to.shared.u64 t, %1; cvt.u32.u64 %0, t; }" : "=r"(a) : "l"(p));
    return a;
}
__device__ __forceinline__ void cpa16(uint32_t dst, const void* src){
    asm volatile("cp.async.cg.shared.global [%0], [%1], 16;" :: "r"(dst), "l"(src) : "memory");
}
#define CP_COMMIT() asm volatile("cp.async.commit_group;" ::: "memory")
#define CP_WAIT2()  asm volatile("cp.async.wait_group 2;" ::: "memory")

__device__ __forceinline__ void mma_f16(float* c, uint32_t a0,uint32_t a1,uint32_t a2,uint32_t a3,
                                        uint32_t b0,uint32_t b1){
    asm("mma.sync.aligned.m16n8k16.row.col.f32.f16.f16.f32 "
        "{%0,%1,%2,%3},{%4,%5,%6,%7},{%8,%9},{%0,%1,%2,%3};"
        : "+f"(c[0]),"+f"(c[1]),"+f"(c[2]),"+f"(c[3])
        : "r"(a0),"r"(a1),"r"(a2),"r"(a3),"r"(b0),"r"(b1));
}

// ---------------- 0. fp32 -> fp16 convert (streaming) -----------------------
__global__ __launch_bounds__(256) void cvt_kernel(const float4* __restrict__ src,
                                                  uint4* __restrict__ dst, int n8){
    int i = blockIdx.x*256 + threadIdx.x;
    int stride = gridDim.x*256;
    for (; i < n8; i += stride){
        float4 a = src[2*i], b = src[2*i+1];
        uint4 o;
        ((__half2*)&o)[0] = __floats2half2_rn(a.x,a.y);
        ((__half2*)&o)[1] = __floats2half2_rn(a.z,a.w);
        ((__half2*)&o)[2] = __floats2half2_rn(b.x,b.y);
        ((__half2*)&o)[3] = __floats2half2_rn(b.z,b.w);
        dst[i] = o;
    }
}

// ---------------- 1. router (exact fp32, 2 tokens/warp) --------------------
__global__ __launch_bounds__(256) void router_kernel(const float* __restrict__ RI,
                                                     const float* __restrict__ WR,
                                                     float* __restrict__ logits){
    int gid = blockIdx.x*256 + threadIdx.x;
    if (blockIdx.x==0){
        if (threadIdx.x < E_) g_cnt[threadIdx.x] = 0;
        else if (threadIdx.x < 2*E_) g_pos[threadIdx.x-E_] = 0;
    }
    int warp = gid >> 5, lane = gid & 31;
    int t0 = warp*2;
    if (t0 >= T_) return;
    const float* xa = RI + (size_t)t0*H_;
    const float* xb = RI + (size_t)(t0+1)*H_;
    float4 ra[8], rb[8];
    #pragma unroll
    for (int j=0;j<8;j++){ ra[j] = *(const float4*)&xa[j*128 + lane*4];
                           rb[j] = *(const float4*)&xb[j*128 + lane*4]; }
    for (int e=0;e<E_;e++){
        const float* w = WR + (size_t)e*H_;
        float s0=0.f, s1=0.f;
        #pragma unroll
        for (int j=0;j<8;j++){
            float4 wv = *(const float4*)&w[j*128 + lane*4];
            s0 += ra[j].x*wv.x + ra[j].y*wv.y + ra[j].z*wv.z + ra[j].w*wv.w;
            s1 += rb[j].x*wv.x + rb[j].y*wv.y + rb[j].z*wv.z + rb[j].w*wv.w;
        }
        #pragma unroll
        for (int off=16;off;off>>=1){
            s0 += __shfl_xor_sync(0xffffffffu, s0, off);
            s1 += __shfl_xor_sync(0xffffffffu, s1, off);
        }
        if (lane==0){ logits[t0*E_+e] = s0; logits[(t0+1)*E_+e] = s1; }
    }
}

// ---------------- 2. top-4 + softmax + counts -------------------------------
__global__ __launch_bounds__(256) void topk_kernel(const float* __restrict__ logits){
    int t    = (blockIdx.x*256 + threadIdx.x) >> 5;
    int lane = threadIdx.x & 31;
    if (t >= T_) return;
    float cur = logits[t*E_ + lane];
    int   idx = lane;
    float vsel[K_]; int isel[K_];
    #pragma unroll
    for (int k=0;k<K_;k++){
        float bv = cur; int bi = idx;
        #pragma unroll
        for (int off=16;off;off>>=1){
            float ov = __shfl_xor_sync(0xffffffffu, bv, off);
            int   oi = __shfl_xor_sync(0xffffffffu, bi, off);
            if (ov > bv || (ov == bv && oi < bi)){ bv = ov; bi = oi; }
        }
        vsel[k]=bv; isel[k]=bi;
        if (idx == bi) cur = -__int_as_float(0x7f800000);
    }
    float mx = vsel[0], den = 0.f, w[K_];
    #pragma unroll
    for (int k=0;k<K_;k++){ w[k] = expf(vsel[k]-mx); den += w[k]; }
    if (lane < K_){
        g_sel[t*K_+lane] = isel[lane];
        g_wgt[t*K_+lane] = w[lane]/den;
        atomicAdd(&g_cnt[isel[lane]], 1);
    }
}

// ---------------- 3. scan + 128-row tile table ------------------------------
__global__ void scan_kernel(){
    if (threadIdx.x != 0) return;
    int acc = 0;
    for (int e=0;e<E_;e++){ g_off[e]=acc; acc += g_cnt[e]; }
    g_off[E_] = acc;
    int tt = 0;
    for (int e=0;e<E_;e++){
        int nt = (g_cnt[e]+127)>>7;
        for (int i=0;i<nt;i++){ g_tileE[tt]=e; g_tileM[tt]=i; tt++; }
    }
    for (; tt<MAXTILES; tt++) g_tileE[tt] = -1;
}

// ---------------- 4. scatter (slot permutation is value-invariant) ----------
__global__ __launch_bounds__(256) void scatter_kernel(){
    int idx = blockIdx.x*256 + threadIdx.x;
    if (idx >= NSLOT) return;
    int e = g_sel[idx];
    int slot = g_off[e] + atomicAdd(&g_pos[e], 1);
    g_slotTok[slot] = idx >> 2;
    g_slotW[slot]   = g_wgt[idx];
    g_slotOf[idx]   = slot;
}

// ---------------- 5. gate+up GEMM: fp16 cp.async 3-stage, 128x64 tile -------
__global__ __launch_bounds__(256,2) void gateup_f16(){
    extern __shared__ char smem[];
    int tile = blockIdx.y;
    int e = g_tileE[tile];
    if (e < 0) return;
    int n0 = blockIdx.x*64;
    int m0 = g_tileM[tile]*128;
    int base = g_off[e];
    int Me   = g_off[e+1] - base;
    int tid = threadIdx.x, lane = tid&31, wid = tid>>5;
    uint32_t sb = smem_u32(smem);

    // A: 512 16B chunks (128 rows x 4), 2/thread
    const __half* srcA[2]; uint32_t dofA[2];
    #pragma unroll
    for (int i=0;i<2;i++){
        int c = tid + i*256, row = c>>2, ch = c&3;
        int tok = g_slotTok[base + m0 + row];
        srcA[i] = g_Xh + (size_t)tok*H_ + ch*8;
        dofA[i] = (uint32_t)row*(AST*2) + ch*16;
    }
    // B: 256 chunks each (64 rows x 4), 1/thread for G and U
    int rowB = tid>>2, chB = tid&3;
    const __half* srcG = g_WGh + (size_t)e*F_*H_ + (size_t)(n0+rowB)*H_ + chB*8;
    const __half* srcU = g_WUh + (size_t)e*F_*H_ + (size_t)(n0+rowB)*H_ + chB*8;
    uint32_t dofB = (uint32_t)rowB*(AST*2) + chB*16;

    const int NK = H_/32;
    #pragma unroll
    for (int kt=0; kt<3; kt++){
        uint32_t s0 = sb + kt*GU_STG_B;
        cpa16(s0 + dofA[0], srcA[0] + kt*32);
        cpa16(s0 + dofA[1], srcA[1] + kt*32);
        cpa16(s0 + GU_GOFF_B + dofB, srcG + kt*32);
        cpa16(s0 + GU_UOFF_B + dofB, srcU + kt*32);
        CP_COMMIT();
    }

    int g = lane>>2, tg = lane&3;
    int wm = wid&3, wn = wid>>2;
    float accG[2][4][4] = {}; float accU[2][4][4] = {};

    for (int kt=0; kt<NK; kt++){
        CP_WAIT2();
        __syncthreads();
        int s = kt - (kt/3)*3;
        const __half* A0 = (const __half*)(smem + s*GU_STG_B);
        const __half* G0 = (const __half*)(smem + s*GU_STG_B + GU_GOFF_B);
        const __half* U0 = (const __half*)(smem + s*GU_STG_B + GU_UOFF_B);
        #pragma unroll
        for (int ks=0; ks<2; ks++){
            int kb = ks*16 + 2*tg;
            uint32_t af[2][4];
            #pragma unroll
            for (int mt=0; mt<2; mt++){
                int r0 = wm*32 + mt*16 + g;
                af[mt][0] = *(const uint32_t*)(A0 + r0*AST     + kb);
                af[mt][1] = *(const uint32_t*)(A0 + (r0+8)*AST + kb);
                af[mt][2] = *(const uint32_t*)(A0 + r0*AST     + kb + 8);
                af[mt][3] = *(const uint32_t*)(A0 + (r0+8)*AST + kb + 8);
            }
            #pragma unroll
            for (int nf=0; nf<4; nf++){
                int nn = wn*32 + nf*8 + g;
                uint32_t bg0 = *(const uint32_t*)(G0 + nn*AST + kb);
                uint32_t bg1 = *(const uint32_t*)(G0 + nn*AST + kb + 8);
                uint32_t bu0 = *(const uint32_t*)(U0 + nn*AST + kb);
                uint32_t bu1 = *(const uint32_t*)(U0 + nn*AST + kb + 8);
                #pragma unroll
                for (int mt=0; mt<2; mt++){
                    mma_f16(accG[mt][nf], af[mt][0],af[mt][1],af[mt][2],af[mt][3], bg0,bg1);
                    mma_f16(accU[mt][nf], af[mt][0],af[mt][1],af[mt][2],af[mt][3], bu0,bu1);
                }
            }
        }
        __syncthreads();
        if (kt+3 < NK){
            uint32_t s0 = sb + s*GU_STG_B;
            int ko = (kt+3)*32;
            cpa16(s0 + dofA[0], srcA[0] + ko);
            cpa16(s0 + dofA[1], srcA[1] + ko);
            cpa16(s0 + GU_GOFF_B + dofB, srcG + ko);
            cpa16(s0 + GU_UOFF_B + dofB, srcU + ko);
        }
        CP_COMMIT();
    }

    // epilogue: h = relu(gate)*up -> fp16
    #pragma unroll
    for (int mt=0; mt<2; mt++){
        #pragma unroll
        for (int half=0; half<2; half++){
            int r = wm*32 + mt*16 + half*8 + g;
            if (m0 + r < Me){
                size_t ob = (size_t)(base+m0+r)*F_ + n0;
                #pragma unroll
                for (int nf=0; nf<4; nf++){
                    int col = wn*32 + nf*8 + 2*tg;
                    float h0 = fmaxf(accG[mt][nf][half*2  ],0.f)*accU[mt][nf][half*2  ];
                    float h1 = fmaxf(accG[mt][nf][half*2+1],0.f)*accU[mt][nf][half*2+1];
                    *(__half2*)&g_Hbuf16[ob + col] = __floats2half2_rn(h0,h1);
                }
            }
        }
    }
}

// ---------------- 6. down GEMM: fp16 cp.async 3-stage, 128x64 tile ----------
__global__ __launch_bounds__(256,2) void down_f16(){
    extern __shared__ char smem[];
    int tile = blockIdx.y;
    int e = g_tileE[tile];
    if (e < 0) return;
    int n0 = blockIdx.x*64;
    int m0 = g_tileM[tile]*128;
    int base = g_off[e];
    int Me   = g_off[e+1] - base;
    int tid = threadIdx.x, lane = tid&31, wid = tid>>5;
    uint32_t sb = smem_u32(smem);

    const __half* srcA[2]; uint32_t dofA[2];
    #pragma unroll
    for (int i=0;i<2;i++){
        int c = tid + i*256, row = c>>2, ch = c&3;
        srcA[i] = g_Hbuf16 + (size_t)(base+m0+row)*F_ + ch*8;
        dofA[i] = (uint32_t)row*(AST*2) + ch*16;
    }
    int rowB = tid>>2, chB = tid&3;
    const __half* srcB = g_WDh + (size_t)e*H_*F_ + (size_t)(n0+rowB)*F_ + chB*8;
    uint32_t dofB = (uint32_t)rowB*(AST*2) + chB*16;

    const int NK = F_/32;
    #pragma unroll
    for (int kt=0; kt<3; kt++){
        uint32_t s0 = sb + kt*DN_STG_B;
        cpa16(s0 + dofA[0], srcA[0] + kt*32);
        cpa16(s0 + dofA[1], srcA[1] + kt*32);
        cpa16(s0 + DN_BOFF_B + dofB, srcB + kt*32);
        CP_COMMIT();
    }

    int g = lane>>2, tg = lane&3;
    int wm = wid&3, wn = wid>>2;
    float acc[2][4][4] = {};

    for (int kt=0; kt<NK; kt++){
        CP_WAIT2();
        __syncthreads();
        int s = kt - (kt/3)*3;
        const __half* A0 = (const __half*)(smem + s*DN_STG_B);
        const __half* B0 = (const __half*)(smem + s*DN_STG_B + DN_BOFF_B);
        #pragma unroll
        for (int ks=0; ks<2; ks++){
            int kb = ks*16 + 2*tg;
            uint32_t af[2][4];
            #pragma unroll
            for (int mt=0; mt<2; mt++){
                int r0 = wm*32 + mt*16 + g;
                af[mt][0] = *(const uint32_t*)(A0 + r0*AST     + kb);
                af[mt][1] = *(const uint32_t*)(A0 + (r0+8)*AST + kb);
                af[mt][2] = *(const uint32_t*)(A0 + r0*AST     + kb + 8);
                af[mt][3] = *(const uint32_t*)(A0 + (r0+8)*AST + kb + 8);
            }
            #pragma unroll
            for (int nf=0; nf<4; nf++){
                int nn = wn*32 + nf*8 + g;
                uint32_t bb0 = *(const uint32_t*)(B0 + nn*AST + kb);
                uint32_t bb1 = *(const uint32_t*)(B0 + nn*AST + kb + 8);
                #pragma unroll
                for (int mt=0; mt<2; mt++)
                    mma_f16(acc[mt][nf], af[mt][0],af[mt][1],af[mt][2],af[mt][3], bb0,bb1);
            }
        }
        __syncthreads();
        if (kt+3 < NK){
            uint32_t s0 = sb + s*DN_STG_B;
            int ko = (kt+3)*32;
            cpa16(s0 + dofA[0], srcA[0] + ko);
            cpa16(s0 + dofA[1], srcA[1] + ko);
            cpa16(s0 + DN_BOFF_B + dofB, srcB + ko);
        }
        CP_COMMIT();
    }

    #pragma unroll
    for (int mt=0; mt<2; mt++){
        #pragma unroll
        for (int half=0; half<2; half++){
            int r = wm*32 + mt*16 + half*8 + g;
            if (m0 + r < Me){
                float wsc = g_slotW[base+m0+r];
                size_t ob = (size_t)(base+m0+r)*H_ + n0;
                #pragma unroll
                for (int nf=0; nf<4; nf++){
                    int col = wn*32 + nf*8 + 2*tg;
                    float2 o;
                    o.x = acc[mt][nf][half*2  ]*wsc;
                    o.y = acc[mt][nf][half*2+1]*wsc;
                    *(float2*)&g_Ybuf[ob + col] = o;
                }
            }
        }
    }
}

// ---------------- 7. deterministic combine ----------------------------------
__global__ __launch_bounds__(256) void combine_kernel(float* __restrict__ out){
    int t = blockIdx.x;
    int h = threadIdx.x * 4;
    float4 acc = make_float4(0.f,0.f,0.f,0.f);
    #pragma unroll
    for (int k=0;k<K_;k++){
        int s = g_slotOf[t*K_+k];
        float4 v = *(const float4*)&g_Ybuf[(size_t)s*H_ + h];
        acc.x += v.x; acc.y += v.y; acc.z += v.z; acc.w += v.w;
    }
    *(float4*)&out[(size_t)t*H_ + h] = acc;
}

// ---------------- launch ----------------------------------------------------
extern "C" void kernel_launch(void* const* d_in, const int* in_sizes, int n_in,
                              void* d_out, int out_size){
    const float* RI = (const float*)d_in[0];
    const float* HS = (const float*)d_in[1];
    const float* WR = (const float*)d_in[2];
    const float* WG = (const float*)d_in[3];
    const float* WU = (const float*)d_in[4];
    const float* WD = (const float*)d_in[5];
    float* out    = (float*)d_out;
    float* logits = out + (size_t)T_*H_;

    cudaFuncSetAttribute(gateup_f16, cudaFuncAttributeMaxDynamicSharedMemorySize, GU_SMEM);
    cudaFuncSetAttribute(down_f16,   cudaFuncAttributeMaxDynamicSharedMemorySize, DN_SMEM);

    __half *wgh, *wuh, *wdh, *xh;
    cudaGetSymbolAddress((void**)&wgh, g_WGh);
    cudaGetSymbolAddress((void**)&wuh, g_WUh);
    cudaGetSymbolAddress((void**)&wdh, g_WDh);
    cudaGetSymbolAddress((void**)&xh,  g_Xh);

    const int NW = E_*F_*H_/8;   // 2,097,152
    const int NX = T_*H_/8;      // 262,144
    cvt_kernel<<<2048, 256>>>((const float4*)WG, (uint4*)wgh, NW);
    cvt_kernel<<<2048, 256>>>((const float4*)WU, (uint4*)wuh, NW);
    cvt_kernel<<<2048, 256>>>((const float4*)WD, (uint4*)wdh, NW);
    cvt_kernel<<<1024, 256>>>((const float4*)HS, (uint4*)xh,  NX);

    router_kernel <<<T_/16, 256>>>(RI, WR, logits);
    topk_kernel   <<<T_/8, 256>>>(logits);
    scan_kernel   <<<1, 32>>>();
    scatter_kernel<<<NSLOT/256, 256>>>();
    gateup_f16    <<<dim3(F_/64, MAXTILES), 256, GU_SMEM>>>();
    down_f16      <<<dim3(H_/64, MAXTILES), 256, DN_SMEM>>>();
    combine_kernel<<<T_, 256>>>(out);
}

// round 8
// speedup vs baseline: 1.6852x; 1.0424x over previous
#include <cuda_runtime.h>
#include <cuda_fp16.h>
#include <cstdint>
#include <cstddef>

#define T_ 2048
#define H_ 1024
#define F_ 512
#define E_ 32
#define K_ 4
#define NSLOT (T_*K_)
#define SLOTPAD (NSLOT+128)
#define MAXTILES 96

#define RSTRIDE 80             // smem row stride in BYTES (40 halves) — LDSM conflict-free
#define GU_STG_B  20480        // A 128*80 + G 64*80 + U 64*80
#define GU_GOFF_B 10240
#define GU_UOFF_B 15360
#define GU_SMEM   (3*GU_STG_B) // 61440
#define DN_STG_B  15360
#define DN_BOFF_B 10240
#define DN_SMEM   (3*DN_STG_B) // 46080

// ---------------- scratch ----------------
__device__ int    g_cnt[E_];
__device__ int    g_pos[E_];
__device__ int    g_off[E_+1];
__device__ int    g_sel[NSLOT];
__device__ float  g_wgt[NSLOT];
__device__ int    g_slotTok[SLOTPAD];
__device__ float  g_slotW[SLOTPAD];
__device__ int    g_slotOf[NSLOT];
__device__ int    g_tileE[MAXTILES];
__device__ int    g_tileM[MAXTILES];
__device__ __half g_WGh[(size_t)E_*F_*H_];
__device__ __half g_WUh[(size_t)E_*F_*H_];
__device__ __half g_WDh[(size_t)E_*H_*F_];
__device__ __half g_Xh [(size_t)T_*H_];
__device__ __half g_Hbuf16[(size_t)SLOTPAD*F_];
__device__ float  g_Ybuf[(size_t)SLOTPAD*H_];

// ---------------- helpers ----------------
__device__ __forceinline__ uint32_t smem_u32(const void* p){
    uint32_t a; asm("{ .reg .u64 t; cvta.to.shared.u64 t, %1; cvt.u32.u64 %0, t; }" : "=r"(a) : "l"(p));
    return a;
}
__device__ __forceinline__ void cpa16(uint32_t dst, const void* src){
    asm volatile("cp.async.cg.shared.global [%0], [%1], 16;" :: "r"(dst), "l"(src) : "memory");
}
#define CP_COMMIT() asm volatile("cp.async.commit_group;" ::: "memory")
#define CP_WAIT2()  asm volatile("cp.async.wait_group 2;" ::: "memory")

__device__ __forceinline__ void mma_f16(float* c, uint32_t a0,uint32_t a1,uint32_t a2,uint32_t a3,
                                        uint32_t b0,uint32_t b1){
    asm("mma.sync.aligned.m16n8k16.row.col.f32.f16.f16.f32 "
        "{%0,%1,%2,%3},{%4,%5,%6,%7},{%8,%9},{%0,%1,%2,%3};"
        : "+f"(c[0]),"+f"(c[1]),"+f"(c[2]),"+f"(c[3])
        : "r"(a0),"r"(a1),"r"(a2),"r"(a3),"r"(b0),"r"(b1));
}
__device__ __forceinline__ void ldsm4(uint32_t& r0,uint32_t& r1,uint32_t& r2,uint32_t& r3,
                                      uint32_t addr){
    asm volatile("ldmatrix.sync.aligned.m8n8.x4.shared.b16 {%0,%1,%2,%3}, [%4];"
        : "=r"(r0),"=r"(r1),"=r"(r2),"=r"(r3) : "r"(addr));
}

// ---------------- 0. fused fp32->fp16 convert + counter zeroing -------------
// 4 chunks (16B out each) per thread, 8 LDG.128 in flight
__global__ __launch_bounds__(256) void cvt_all(const float4* __restrict__ wg,
                                               const float4* __restrict__ wu,
                                               const float4* __restrict__ wd,
                                               const float4* __restrict__ hs){
    if (blockIdx.x==0 && threadIdx.x < E_){ g_cnt[threadIdx.x]=0; g_pos[threadIdx.x]=0; }
    const int NW = E_*F_*H_/8;     // 2097152 chunks per weight tensor
    const int NX = T_*H_/8;        // 262144
    long c0 = ((long)blockIdx.x*256 + threadIdx.x)*4;
    if (c0 >= 3L*NW + NX) return;
    const float4* src; uint4* dst; long base;
    if      (c0 <    NW){ src=wg; dst=(uint4*)g_WGh; base=0; }
    else if (c0 < 2L*NW){ src=wu; dst=(uint4*)g_WUh; base=NW; }
    else if (c0 < 3L*NW){ src=wd; dst=(uint4*)g_WDh; base=2L*NW; }
    else                { src=hs; dst=(uint4*)g_Xh;  base=3L*NW; }
    long i = c0 - base;
    float4 a[8];
    #pragma unroll
    for (int j=0;j<8;j++) a[j] = src[2*i + j];
    #pragma unroll
    for (int j=0;j<4;j++){
        uint4 o;
        ((__half2*)&o)[0] = __floats2half2_rn(a[2*j].x,   a[2*j].y);
        ((__half2*)&o)[1] = __floats2half2_rn(a[2*j].z,   a[2*j].w);
        ((__half2*)&o)[2] = __floats2half2_rn(a[2*j+1].x, a[2*j+1].y);
        ((__half2*)&o)[3] = __floats2half2_rn(a[2*j+1].z, a[2*j+1].w);
        dst[i+j] = o;
    }
}

// ---------------- 1. router + top-4 + softmax + counts (fused) --------------
__global__ __launch_bounds__(256) void router_kernel(const float* __restrict__ RI,
                                                     const float* __restrict__ WR,
                                                     float* __restrict__ logits){
    int gid = blockIdx.x*256 + threadIdx.x;
    int warp = gid >> 5, lane = gid & 31;
    int t0 = warp*2;
    if (t0 >= T_) return;
    const float* xa = RI + (size_t)t0*H_;
    const float* xb = RI + (size_t)(t0+1)*H_;
    float4 ra[8], rb[8];
    #pragma unroll
    for (int j=0;j<8;j++){ ra[j] = *(const float4*)&xa[j*128 + lane*4];
                           rb[j] = *(const float4*)&xb[j*128 + lane*4]; }
    float l0 = 0.f, l1 = 0.f;
    for (int e=0;e<E_;e++){
        const float* w = WR + (size_t)e*H_;
        float s0=0.f, s1=0.f;
        #pragma unroll
        for (int j=0;j<8;j++){
            float4 wv = *(const float4*)&w[j*128 + lane*4];
            s0 += ra[j].x*wv.x + ra[j].y*wv.y + ra[j].z*wv.z + ra[j].w*wv.w;
            s1 += rb[j].x*wv.x + rb[j].y*wv.y + rb[j].z*wv.z + rb[j].w*wv.w;
        }
        #pragma unroll
        for (int off=16;off;off>>=1){
            s0 += __shfl_xor_sync(0xffffffffu, s0, off);
            s1 += __shfl_xor_sync(0xffffffffu, s1, off);
        }
        if (lane == e){ l0 = s0; l1 = s1; }
    }
    logits[(size_t)t0*E_ + lane]     = l0;
    logits[(size_t)(t0+1)*E_ + lane] = l1;

    #pragma unroll
    for (int tok=0; tok<2; tok++){
        int t = t0 + tok;
        float cur = (tok==0) ? l0 : l1;
        int idx = lane;
        float vsel[K_]; int isel[K_];
        #pragma unroll
        for (int k=0;k<K_;k++){
            float bv = cur; int bi = idx;
            #pragma unroll
            for (int off=16;off;off>>=1){
                float ov = __shfl_xor_sync(0xffffffffu, bv, off);
                int   oi = __shfl_xor_sync(0xffffffffu, bi, off);
                if (ov > bv || (ov == bv && oi < bi)){ bv = ov; bi = oi; }
            }
            vsel[k]=bv; isel[k]=bi;
            if (idx == bi) cur = -__int_as_float(0x7f800000);
        }
        float mx = vsel[0], den = 0.f, w[K_];
        #pragma unroll
        for (int k=0;k<K_;k++){ w[k] = expf(vsel[k]-mx); den += w[k]; }
        if (lane < K_){
            g_sel[t*K_+lane] = isel[lane];
            g_wgt[t*K_+lane] = w[lane]/den;
            atomicAdd(&g_cnt[isel[lane]], 1);
        }
    }
}

// ---------------- 3. scan + 128-row tile table ------------------------------
__global__ void scan_kernel(){
    if (threadIdx.x != 0) return;
    int acc = 0;
    for (int e=0;e<E_;e++){ g_off[e]=acc; acc += g_cnt[e]; }
    g_off[E_] = acc;
    int tt = 0;
    for (int e=0;e<E_;e++){
        int nt = (g_cnt[e]+127)>>7;
        for (int i=0;i<nt;i++){ g_tileE[tt]=e; g_tileM[tt]=i; tt++; }
    }
    for (; tt<MAXTILES; tt++) g_tileE[tt] = -1;
}

// ---------------- 4. scatter (slot permutation is value-invariant) ----------
__global__ __launch_bounds__(256) void scatter_kernel(){
    int idx = blockIdx.x*256 + threadIdx.x;
    if (idx >= NSLOT) return;
    int e = g_sel[idx];
    int slot = g_off[e] + atomicAdd(&g_pos[e], 1);
    g_slotTok[slot] = idx >> 2;
    g_slotW[slot]   = g_wgt[idx];
    g_slotOf[idx]   = slot;
}

// ---------------- 5. gate+up GEMM: fp16, cp.async 3-stage, ldmatrix ---------
__global__ __launch_bounds__(256,2) void gateup_f16(){
    extern __shared__ char smem[];
    int tile = blockIdx.y;
    int e = g_tileE[tile];
    if (e < 0) return;
    int n0 = blockIdx.x*64;
    int m0 = g_tileM[tile]*128;
    int base = g_off[e];
    int Me   = g_off[e+1] - base;
    int tid = threadIdx.x, lane = tid&31, wid = tid>>5;
    uint32_t sb = smem_u32(smem);

    // producers: A 512 chunks (2/thread), B 256 chunks each (1/thread)
    const __half* srcA[2]; uint32_t dofA[2];
    #pragma unroll
    for (int i=0;i<2;i++){
        int c = tid + i*256, row = c>>2, ch = c&3;
        int tok = g_slotTok[base + m0 + row];
        srcA[i] = g_Xh + (size_t)tok*H_ + ch*8;
        dofA[i] = (uint32_t)row*RSTRIDE + ch*16;
    }
    int rowB = tid>>2, chB = tid&3;
    const __half* srcG = g_WGh + (size_t)e*F_*H_ + (size_t)(n0+rowB)*H_ + chB*8;
    const __half* srcU = g_WUh + (size_t)e*F_*H_ + (size_t)(n0+rowB)*H_ + chB*8;
    uint32_t dofB = (uint32_t)rowB*RSTRIDE + chB*16;

    const int NK = H_/32;
    #pragma unroll
    for (int kt=0; kt<3; kt++){
        uint32_t s0 = sb + kt*GU_STG_B;
        cpa16(s0 + dofA[0], srcA[0] + kt*32);
        cpa16(s0 + dofA[1], srcA[1] + kt*32);
        cpa16(s0 + GU_GOFF_B + dofB, srcG + kt*32);
        cpa16(s0 + GU_UOFF_B + dofB, srcU + kt*32);
        CP_COMMIT();
    }

    int g = lane>>2, tg = lane&3;
    int wm = wid&3, wn = wid>>2;
    // ldmatrix per-lane offsets
    uint32_t aOff = (uint32_t)(wm*32 + (lane&7) + ((lane>>3)&1)*8)*RSTRIDE + ((lane>>4)&1)*16;
    uint32_t bOff = (uint32_t)(wn*32 + (lane&7) + ((lane>>4)&1)*8)*RSTRIDE + ((lane>>3)&1)*16;

    float accG[2][4][4] = {}; float accU[2][4][4] = {};

    for (int kt=0; kt<NK; kt++){
        CP_WAIT2();
        __syncthreads();
        int s = kt - (kt/3)*3;
        uint32_t sA = sb + s*GU_STG_B;
        uint32_t sG = sA + GU_GOFF_B;
        uint32_t sU = sA + GU_UOFF_B;
        #pragma unroll
        for (int ks=0; ks<2; ks++){
            uint32_t a0[4], a1[4], bg[8], bu[8];
            ldsm4(a0[0],a0[1],a0[2],a0[3], sA + aOff + ks*32);
            ldsm4(a1[0],a1[1],a1[2],a1[3], sA + aOff + 16*RSTRIDE + ks*32);
            ldsm4(bg[0],bg[1],bg[2],bg[3], sG + bOff + ks*32);
            ldsm4(bg[4],bg[5],bg[6],bg[7], sG + bOff + 16*RSTRIDE + ks*32);
            ldsm4(bu[0],bu[1],bu[2],bu[3], sU + bOff + ks*32);
            ldsm4(bu[4],bu[5],bu[6],bu[7], sU + bOff + 16*RSTRIDE + ks*32);
            #pragma unroll
            for (int nf=0; nf<4; nf++){
                mma_f16(accG[0][nf], a0[0],a0[1],a0[2],a0[3], bg[nf*2],bg[nf*2+1]);
                mma_f16(accG[1][nf], a1[0],a1[1],a1[2],a1[3], bg[nf*2],bg[nf*2+1]);
                mma_f16(accU[0][nf], a0[0],a0[1],a0[2],a0[3], bu[nf*2],bu[nf*2+1]);
                mma_f16(accU[1][nf], a1[0],a1[1],a1[2],a1[3], bu[nf*2],bu[nf*2+1]);
            }
        }
        __syncthreads();
        if (kt+3 < NK){
            uint32_t s0 = sb + s*GU_STG_B;
            int ko = (kt+3)*32;
            cpa16(s0 + dofA[0], srcA[0] + ko);
            cpa16(s0 + dofA[1], srcA[1] + ko);
            cpa16(s0 + GU_GOFF_B + dofB, srcG + ko);
            cpa16(s0 + GU_UOFF_B + dofB, srcU + ko);
        }
        CP_COMMIT();
    }

    // epilogue: h = relu(gate)*up -> fp16
    #pragma unroll
    for (int mt=0; mt<2; mt++){
        #pragma unroll
        for (int half=0; half<2; half++){
            int r = wm*32 + mt*16 + half*8 + g;
            if (m0 + r < Me){
                size_t ob = (size_t)(base+m0+r)*F_ + n0;
                #pragma unroll
                for (int nf=0; nf<4; nf++){
                    int col = wn*32 + nf*8 + 2*tg;
                    float h0 = fmaxf(accG[mt][nf][half*2  ],0.f)*accU[mt][nf][half*2  ];
                    float h1 = fmaxf(accG[mt][nf][half*2+1],0.f)*accU[mt][nf][half*2+1];
                    *(__half2*)&g_Hbuf16[ob + col] = __floats2half2_rn(h0,h1);
                }
            }
        }
    }
}

// ---------------- 6. down GEMM: fp16, cp.async 3-stage, ldmatrix ------------
__global__ __launch_bounds__(256,2) void down_f16(){
    extern __shared__ char smem[];
    int tile = blockIdx.y;
    int e = g_tileE[tile];
    if (e < 0) return;
    int n0 = blockIdx.x*64;
    int m0 = g_tileM[tile]*128;
    int base = g_off[e];
    int Me   = g_off[e+1] - base;
    int tid = threadIdx.x, lane = tid&31, wid = tid>>5;
    uint32_t sb = smem_u32(smem);

    const __half* srcA[2]; uint32_t dofA[2];
    #pragma unroll
    for (int i=0;i<2;i++){
        int c = tid + i*256, row = c>>2, ch = c&3;
        srcA[i] = g_Hbuf16 + (size_t)(base+m0+row)*F_ + ch*8;
        dofA[i] = (uint32_t)row*RSTRIDE + ch*16;
    }
    int rowB = tid>>2, chB = tid&3;
    const __half* srcB = g_WDh + (size_t)e*H_*F_ + (size_t)(n0+rowB)*F_ + chB*8;
    uint32_t dofB = (uint32_t)rowB*RSTRIDE + chB*16;

    const int NK = F_/32;
    #pragma unroll
    for (int kt=0; kt<3; kt++){
        uint32_t s0 = sb + kt*DN_STG_B;
        cpa16(s0 + dofA[0], srcA[0] + kt*32);
        cpa16(s0 + dofA[1], srcA[1] + kt*32);
        cpa16(s0 + DN_BOFF_B + dofB, srcB + kt*32);
        CP_COMMIT();
    }

    int g = lane>>2, tg = lane&3;
    int wm = wid&3, wn = wid>>2;
    uint32_t aOff = (uint32_t)(wm*32 + (lane&7) + ((lane>>3)&1)*8)*RSTRIDE + ((lane>>4)&1)*16;
    uint32_t bOff = (uint32_t)(wn*32 + (lane&7) + ((lane>>4)&1)*8)*RSTRIDE + ((lane>>3)&1)*16;

    float acc[2][4][4] = {};

    for (int kt=0; kt<NK; kt++){
        CP_WAIT2();
        __syncthreads();
        int s = kt - (kt/3)*3;
        uint32_t sA = sb + s*DN_STG_B;
        uint32_t sB = sA + DN_BOFF_B;
        #pragma unroll
        for (int ks=0; ks<2; ks++){
            uint32_t a0[4], a1[4], bb[8];
            ldsm4(a0[0],a0[1],a0[2],a0[3], sA + aOff + ks*32);
            ldsm4(a1[0],a1[1],a1[2],a1[3], sA + aOff + 16*RSTRIDE + ks*32);
            ldsm4(bb[0],bb[1],bb[2],bb[3], sB + bOff + ks*32);
            ldsm4(bb[4],bb[5],bb[6],bb[7], sB + bOff + 16*RSTRIDE + ks*32);
            #pragma unroll
            for (int nf=0; nf<4; nf++){
                mma_f16(acc[0][nf], a0[0],a0[1],a0[2],a0[3], bb[nf*2],bb[nf*2+1]);
                mma_f16(acc[1][nf], a1[0],a1[1],a1[2],a1[3], bb[nf*2],bb[nf*2+1]);
            }
        }
        __syncthreads();
        if (kt+3 < NK){
            uint32_t s0 = sb + s*DN_STG_B;
            int ko = (kt+3)*32;
            cpa16(s0 + dofA[0], srcA[0] + ko);
            cpa16(s0 + dofA[1], srcA[1] + ko);
            cpa16(s0 + DN_BOFF_B + dofB, srcB + ko);
        }
        CP_COMMIT();
    }

    #pragma unroll
    for (int mt=0; mt<2; mt++){
        #pragma unroll
        for (int half=0; half<2; half++){
            int r = wm*32 + mt*16 + half*8 + g;
            if (m0 + r < Me){
                float wsc = g_slotW[base+m0+r];
                size_t ob = (size_t)(base+m0+r)*H_ + n0;
                #pragma unroll
                for (int nf=0; nf<4; nf++){
                    int col = wn*32 + nf*8 + 2*tg;
                    float2 o;
                    o.x = acc[mt][nf][half*2  ]*wsc;
                    o.y = acc[mt][nf][half*2+1]*wsc;
                    *(float2*)&g_Ybuf[ob + col] = o;
                }
            }
        }
    }
}

// ---------------- 7. deterministic combine ----------------------------------
__global__ __launch_bounds__(256) void combine_kernel(float* __restrict__ out){
    int t = blockIdx.x;
    int h = threadIdx.x * 4;
    float4 acc = make_float4(0.f,0.f,0.f,0.f);
    #pragma unroll
    for (int k=0;k<K_;k++){
        int s = g_slotOf[t*K_+k];
        float4 v = *(const float4*)&g_Ybuf[(size_t)s*H_ + h];
        acc.x += v.x; acc.y += v.y; acc.z += v.z; acc.w += v.w;
    }
    *(float4*)&out[(size_t)t*H_ + h] = acc;
}

// ---------------- launch ----------------------------------------------------
extern "C" void kernel_launch(void* const* d_in, const int* in_sizes, int n_in,
                              void* d_out, int out_size){
    const float* RI = (const float*)d_in[0];
    const float* HS = (const float*)d_in[1];
    const float* WR = (const float*)d_in[2];
    const float* WG = (const float*)d_in[3];
    const float* WU = (const float*)d_in[4];
    const float* WD = (const float*)d_in[5];
    float* out    = (float*)d_out;
    float* logits = out + (size_t)T_*H_;

    cudaFuncSetAttribute(gateup_f16, cudaFuncAttributeMaxDynamicSharedMemorySize, GU_SMEM);
    cudaFuncSetAttribute(down_f16,   cudaFuncAttributeMaxDynamicSharedMemorySize, DN_SMEM);

    // total chunks = 3*2097152 + 262144 = 6553600; /4 per thread /256 per block
    cvt_all       <<<6400, 256>>>((const float4*)WG, (const float4*)WU,
                                  (const float4*)WD, (const float4*)HS);
    router_kernel <<<T_/16, 256>>>(RI, WR, logits);
    scan_kernel   <<<1, 32>>>();
    scatter_kernel<<<NSLOT/256, 256>>>();
    gateup_f16    <<<dim3(F_/64, MAXTILES), 256, GU_SMEM>>>();
    down_f16      <<<dim3(H_/64, MAXTILES), 256, DN_SMEM>>>();
    combine_kernel<<<T_, 256>>>(out);
}

// round 9
// speedup vs baseline: 1.7283x; 1.0256x over previous
#include <cuda_runtime.h>
#include <cuda_fp16.h>
#include <cstdint>
#include <cstddef>

#define T_ 2048
#define H_ 1024
#define F_ 512
#define E_ 32
#define K_ 4
#define NSLOT (T_*K_)
#define SLOTPAD (NSLOT+128)
#define MAXTILES 96

#define RSTRIDE 144            // bytes per smem row (64 halves + 8 pad) — LDSM conflict-free
#define GU_STG_B  36864        // A 128*144 + G 64*144 + U 64*144
#define GU_GOFF_B 18432
#define GU_UOFF_B 27648
#define GU_SMEM   (3*GU_STG_B) // 110592
#define DN_STG_B  27648
#define DN_BOFF_B 18432
#define DN_SMEM   (3*DN_STG_B) // 82944

// ---------------- scratch ----------------
__device__ int    g_cnt[E_];
__device__ int    g_off[E_+1];
__device__ int    g_sel[NSLOT];
__device__ float  g_wgt[NSLOT];
__device__ int    g_slotTok[SLOTPAD];
__device__ float  g_slotW[SLOTPAD];
__device__ int    g_tileE[MAXTILES];
__device__ int    g_tileM[MAXTILES];
__device__ __half g_WGh[(size_t)E_*F_*H_];
__device__ __half g_WUh[(size_t)E_*F_*H_];
__device__ __half g_WDh[(size_t)E_*H_*F_];
__device__ __half g_Xh [(size_t)T_*H_];
__device__ __half g_Hbuf16[(size_t)SLOTPAD*F_];

// ---------------- helpers ----------------
__device__ __forceinline__ uint32_t smem_u32(const void* p){
    uint32_t a; asm("{ .reg .u64 t; cvta.to.shared.u64 t, %1; cvt.u32.u64 %0, t; }" : "=r"(a) : "l"(p));
    return a;
}
__device__ __forceinline__ void cpa16(uint32_t dst, const void* src){
    asm volatile("cp.async.cg.shared.global [%0], [%1], 16;" :: "r"(dst), "l"(src) : "memory");
}
#define CP_COMMIT() asm volatile("cp.async.commit_group;" ::: "memory")
#define CP_WAIT2()  asm volatile("cp.async.wait_group 2;" ::: "memory")

__device__ __forceinline__ void mma_f16(float* c, uint32_t a0,uint32_t a1,uint32_t a2,uint32_t a3,
                                        uint32_t b0,uint32_t b1){
    asm("mma.sync.aligned.m16n8k16.row.col.f32.f16.f16.f32 "
        "{%0,%1,%2,%3},{%4,%5,%6,%7},{%8,%9},{%0,%1,%2,%3};"
        : "+f"(c[0]),"+f"(c[1]),"+f"(c[2]),"+f"(c[3])
        : "r"(a0),"r"(a1),"r"(a2),"r"(a3),"r"(b0),"r"(b1));
}
__device__ __forceinline__ void ldsm4(uint32_t& r0,uint32_t& r1,uint32_t& r2,uint32_t& r3,
                                      uint32_t addr){
    asm volatile("ldmatrix.sync.aligned.m8n8.x4.shared.b16 {%0,%1,%2,%3}, [%4];"
        : "=r"(r0),"=r"(r1),"=r"(r2),"=r"(r3) : "r"(addr));
}

// ---------------- 1. fused convert + router (router = blocks 0..127) --------
__global__ __launch_bounds__(256) void cvtrouter(const float4* __restrict__ wg,
                                                 const float4* __restrict__ wu,
                                                 const float4* __restrict__ wd,
                                                 const float4* __restrict__ hs,
                                                 const float* __restrict__ RI,
                                                 const float* __restrict__ WR,
                                                 float* __restrict__ logits){
    if (blockIdx.x < 128){
        // ---- router + top-4 + softmax + counts ----
        int gid = blockIdx.x*256 + threadIdx.x;
        int warp = gid >> 5, lane = gid & 31;
        int t0 = warp*2;
        const float* xa = RI + (size_t)t0*H_;
        const float* xb = RI + (size_t)(t0+1)*H_;
        float4 ra[8], rb[8];
        #pragma unroll
        for (int j=0;j<8;j++){ ra[j] = *(const float4*)&xa[j*128 + lane*4];
                               rb[j] = *(const float4*)&xb[j*128 + lane*4]; }
        float l0 = 0.f, l1 = 0.f;
        for (int e=0;e<E_;e++){
            const float* w = WR + (size_t)e*H_;
            float s0=0.f, s1=0.f;
            #pragma unroll
            for (int j=0;j<8;j++){
                float4 wv = *(const float4*)&w[j*128 + lane*4];
                s0 += ra[j].x*wv.x + ra[j].y*wv.y + ra[j].z*wv.z + ra[j].w*wv.w;
                s1 += rb[j].x*wv.x + rb[j].y*wv.y + rb[j].z*wv.z + rb[j].w*wv.w;
            }
            #pragma unroll
            for (int off=16;off;off>>=1){
                s0 += __shfl_xor_sync(0xffffffffu, s0, off);
                s1 += __shfl_xor_sync(0xffffffffu, s1, off);
            }
            if (lane == e){ l0 = s0; l1 = s1; }
        }
        logits[(size_t)t0*E_ + lane]     = l0;
        logits[(size_t)(t0+1)*E_ + lane] = l1;
        #pragma unroll
        for (int tok=0; tok<2; tok++){
            int t = t0 + tok;
            float cur = (tok==0) ? l0 : l1;
            int idx = lane;
            float vsel[K_]; int isel[K_];
            #pragma unroll
            for (int k=0;k<K_;k++){
                float bv = cur; int bi = idx;
                #pragma unroll
                for (int off=16;off;off>>=1){
                    float ov = __shfl_xor_sync(0xffffffffu, bv, off);
                    int   oi = __shfl_xor_sync(0xffffffffu, bi, off);
                    if (ov > bv || (ov == bv && oi < bi)){ bv = ov; bi = oi; }
                }
                vsel[k]=bv; isel[k]=bi;
                if (idx == bi) cur = -__int_as_float(0x7f800000);
            }
            float mx = vsel[0], den = 0.f, w[K_];
            #pragma unroll
            for (int k=0;k<K_;k++){ w[k] = expf(vsel[k]-mx); den += w[k]; }
            if (lane < K_){
                g_sel[t*K_+lane] = isel[lane];
                g_wgt[t*K_+lane] = w[lane]/den;
                atomicAdd(&g_cnt[isel[lane]], 1);
            }
        }
        return;
    }
    // ---- fp32 -> fp16 convert, 4 chunks/thread ----
    const int NW = E_*F_*H_/8;
    const int NX = T_*H_/8;
    long c0 = ((long)(blockIdx.x-128)*256 + threadIdx.x)*4;
    if (c0 >= 3L*NW + NX) return;
    const float4* src; uint4* dst; long base;
    if      (c0 <    NW){ src=wg; dst=(uint4*)g_WGh; base=0; }
    else if (c0 < 2L*NW){ src=wu; dst=(uint4*)g_WUh; base=NW; }
    else if (c0 < 3L*NW){ src=wd; dst=(uint4*)g_WDh; base=2L*NW; }
    else                { src=hs; dst=(uint4*)g_Xh;  base=3L*NW; }
    long i = c0 - base;
    float4 a[8];
    #pragma unroll
    for (int j=0;j<8;j++) a[j] = src[2*i + j];
    #pragma unroll
    for (int j=0;j<4;j++){
        uint4 o;
        ((__half2*)&o)[0] = __floats2half2_rn(a[2*j].x,   a[2*j].y);
        ((__half2*)&o)[1] = __floats2half2_rn(a[2*j].z,   a[2*j].w);
        ((__half2*)&o)[2] = __floats2half2_rn(a[2*j+1].x, a[2*j+1].y);
        ((__half2*)&o)[3] = __floats2half2_rn(a[2*j+1].z, a[2*j+1].w);
        dst[i+j] = o;
    }
}

// ---------------- 2. scan + scatter + tile table (one block) ----------------
__global__ __launch_bounds__(256) void scanscatter(){
    __shared__ int soff[E_];
    __shared__ int spos[E_];
    int tid = threadIdx.x;
    if (tid < E_) spos[tid] = 0;
    if (tid == 0){
        int acc = 0;
        for (int e=0;e<E_;e++){ soff[e]=acc; g_off[e]=acc; acc += g_cnt[e]; }
        g_off[E_] = acc;
        int tt = 0;
        for (int e=0;e<E_;e++){
            int nt = (g_cnt[e]+127)>>7;
            for (int i=0;i<nt;i++){ g_tileE[tt]=e; g_tileM[tt]=i; tt++; }
        }
        for (; tt<MAXTILES; tt++) g_tileE[tt] = -1;
    }
    __syncthreads();
    for (int idx = tid; idx < NSLOT; idx += 256){
        int e = g_sel[idx];
        int slot = soff[e] + atomicAdd(&spos[e], 1);
        g_slotTok[slot] = idx >> 2;
        g_slotW[slot]   = g_wgt[idx];
    }
}

// ---------------- 3. gate+up GEMM: fp16, cp.async 3-stage, K-chunk 64 -------
__global__ __launch_bounds__(256,2) void gateup_f16(){
    extern __shared__ char smem[];
    int tile = blockIdx.y;
    int e = g_tileE[tile];
    if (e < 0) return;
    int n0 = blockIdx.x*64;
    int m0 = g_tileM[tile]*128;
    int base = g_off[e];
    int Me   = g_off[e+1] - base;
    int tid = threadIdx.x, lane = tid&31, wid = tid>>5;
    uint32_t sb = smem_u32(smem);

    // producers: A 1024 chunks (4/thread), G/U 512 chunks (2/thread)
    const __half* srcA[4]; uint32_t dofA[4];
    #pragma unroll
    for (int i=0;i<4;i++){
        int c = tid + i*256, row = c>>3, ch = c&7;
        int tok = g_slotTok[base + m0 + row];
        srcA[i] = g_Xh + (size_t)tok*H_ + ch*8;
        dofA[i] = (uint32_t)row*RSTRIDE + ch*16;
    }
    const __half* srcG[2]; const __half* srcU[2]; uint32_t dofB[2];
    #pragma unroll
    for (int i=0;i<2;i++){
        int c = tid + i*256, row = c>>3, ch = c&7;
        srcG[i] = g_WGh + (size_t)e*F_*H_ + (size_t)(n0+row)*H_ + ch*8;
        srcU[i] = g_WUh + (size_t)e*F_*H_ + (size_t)(n0+row)*H_ + ch*8;
        dofB[i] = (uint32_t)row*RSTRIDE + ch*16;
    }

    const int NK = H_/64;   // 16
    #pragma unroll
    for (int kt=0; kt<3; kt++){
        uint32_t s0 = sb + kt*GU_STG_B;
        #pragma unroll
        for (int i=0;i<4;i++) cpa16(s0 + dofA[i], srcA[i] + kt*64);
        #pragma unroll
        for (int i=0;i<2;i++){
            cpa16(s0 + GU_GOFF_B + dofB[i], srcG[i] + kt*64);
            cpa16(s0 + GU_UOFF_B + dofB[i], srcU[i] + kt*64);
        }
        CP_COMMIT();
    }

    int g = lane>>2, tg = lane&3;
    int wm = wid&3, wn = wid>>2;
    uint32_t aOff = (uint32_t)(wm*32 + (lane&7) + ((lane>>3)&1)*8)*RSTRIDE + ((lane>>4)&1)*16;
    uint32_t bOff = (uint32_t)(wn*32 + (lane&7) + ((lane>>4)&1)*8)*RSTRIDE + ((lane>>3)&1)*16;

    float accG[2][4][4] = {}; float accU[2][4][4] = {};

    for (int kt=0; kt<NK; kt++){
        CP_WAIT2();
        __syncthreads();
        int s = kt - (kt/3)*3;
        uint32_t sA = sb + s*GU_STG_B;
        uint32_t sG = sA + GU_GOFF_B;
        uint32_t sU = sA + GU_UOFF_B;
        #pragma unroll
        for (int ks=0; ks<4; ks++){
            uint32_t a0[4], a1[4], bg[8], bu[8];
            ldsm4(a0[0],a0[1],a0[2],a0[3], sA + aOff + ks*32);
            ldsm4(a1[0],a1[1],a1[2],a1[3], sA + aOff + 16*RSTRIDE + ks*32);
            ldsm4(bg[0],bg[1],bg[2],bg[3], sG + bOff + ks*32);
            ldsm4(bg[4],bg[5],bg[6],bg[7], sG + bOff + 16*RSTRIDE + ks*32);
            ldsm4(bu[0],bu[1],bu[2],bu[3], sU + bOff + ks*32);
            ldsm4(bu[4],bu[5],bu[6],bu[7], sU + bOff + 16*RSTRIDE + ks*32);
            #pragma unroll
            for (int nf=0; nf<4; nf++){
                mma_f16(accG[0][nf], a0[0],a0[1],a0[2],a0[3], bg[nf*2],bg[nf*2+1]);
                mma_f16(accG[1][nf], a1[0],a1[1],a1[2],a1[3], bg[nf*2],bg[nf*2+1]);
                mma_f16(accU[0][nf], a0[0],a0[1],a0[2],a0[3], bu[nf*2],bu[nf*2+1]);
                mma_f16(accU[1][nf], a1[0],a1[1],a1[2],a1[3], bu[nf*2],bu[nf*2+1]);
            }
        }
        __syncthreads();
        if (kt+3 < NK){
            uint32_t s0 = sb + s*GU_STG_B;
            int ko = (kt+3)*64;
            #pragma unroll
            for (int i=0;i<4;i++) cpa16(s0 + dofA[i], srcA[i] + ko);
            #pragma unroll
            for (int i=0;i<2;i++){
                cpa16(s0 + GU_GOFF_B + dofB[i], srcG[i] + ko);
                cpa16(s0 + GU_UOFF_B + dofB[i], srcU[i] + ko);
            }
        }
        CP_COMMIT();
    }

    #pragma unroll
    for (int mt=0; mt<2; mt++){
        #pragma unroll
        for (int half=0; half<2; half++){
            int r = wm*32 + mt*16 + half*8 + g;
            if (m0 + r < Me){
                size_t ob = (size_t)(base+m0+r)*F_ + n0;
                #pragma unroll
                for (int nf=0; nf<4; nf++){
                    int col = wn*32 + nf*8 + 2*tg;
                    float h0 = fmaxf(accG[mt][nf][half*2  ],0.f)*accU[mt][nf][half*2  ];
                    float h1 = fmaxf(accG[mt][nf][half*2+1],0.f)*accU[mt][nf][half*2+1];
                    *(__half2*)&g_Hbuf16[ob + col] = __floats2half2_rn(h0,h1);
                }
            }
        }
    }
}

// ---------------- 4. down GEMM: fp16, K-chunk 64, atomic epilogue -----------
__global__ __launch_bounds__(256,2) void down_f16(float* __restrict__ out){
    extern __shared__ char smem[];
    int tile = blockIdx.y;
    int e = g_tileE[tile];
    if (e < 0) return;
    int n0 = blockIdx.x*64;
    int m0 = g_tileM[tile]*128;
    int base = g_off[e];
    int Me   = g_off[e+1] - base;
    int tid = threadIdx.x, lane = tid&31, wid = tid>>5;
    uint32_t sb = smem_u32(smem);

    const __half* srcA[4]; uint32_t dofA[4];
    #pragma unroll
    for (int i=0;i<4;i++){
        int c = tid + i*256, row = c>>3, ch = c&7;
        srcA[i] = g_Hbuf16 + (size_t)(base+m0+row)*F_ + ch*8;
        dofA[i] = (uint32_t)row*RSTRIDE + ch*16;
    }
    const __half* srcB[2]; uint32_t dofB[2];
    #pragma unroll
    for (int i=0;i<2;i++){
        int c = tid + i*256, row = c>>3, ch = c&7;
        srcB[i] = g_WDh + (size_t)e*H_*F_ + (size_t)(n0+row)*F_ + ch*8;
        dofB[i] = (uint32_t)row*RSTRIDE + ch*16;
    }

    const int NK = F_/64;   // 8
    #pragma unroll
    for (int kt=0; kt<3; kt++){
        uint32_t s0 = sb + kt*DN_STG_B;
        #pragma unroll
        for (int i=0;i<4;i++) cpa16(s0 + dofA[i], srcA[i] + kt*64);
        #pragma unroll
        for (int i=0;i<2;i++) cpa16(s0 + DN_BOFF_B + dofB[i], srcB[i] + kt*64);
        CP_COMMIT();
    }

    int g = lane>>2, tg = lane&3;
    int wm = wid&3, wn = wid>>2;
    uint32_t aOff = (uint32_t)(wm*32 + (lane&7) + ((lane>>3)&1)*8)*RSTRIDE + ((lane>>4)&1)*16;
    uint32_t bOff = (uint32_t)(wn*32 + (lane&7) + ((lane>>4)&1)*8)*RSTRIDE + ((lane>>3)&1)*16;

    float acc[2][4][4] = {};

    for (int kt=0; kt<NK; kt++){
        CP_WAIT2();
        __syncthreads();
        int s = kt - (kt/3)*3;
        uint32_t sA = sb + s*DN_STG_B;
        uint32_t sB = sA + DN_BOFF_B;
        #pragma unroll
        for (int ks=0; ks<4; ks++){
            uint32_t a0[4], a1[4], bb[8];
            ldsm4(a0[0],a0[1],a0[2],a0[3], sA + aOff + ks*32);
            ldsm4(a1[0],a1[1],a1[2],a1[3], sA + aOff + 16*RSTRIDE + ks*32);
            ldsm4(bb[0],bb[1],bb[2],bb[3], sB + bOff + ks*32);
            ldsm4(bb[4],bb[5],bb[6],bb[7], sB + bOff + 16*RSTRIDE + ks*32);
            #pragma unroll
            for (int nf=0; nf<4; nf++){
                mma_f16(acc[0][nf], a0[0],a0[1],a0[2],a0[3], bb[nf*2],bb[nf*2+1]);
                mma_f16(acc[1][nf], a1[0],a1[1],a1[2],a1[3], bb[nf*2],bb[nf*2+1]);
            }
        }
        __syncthreads();
        if (kt+3 < NK){
            uint32_t s0 = sb + s*DN_STG_B;
            int ko = (kt+3)*64;
            #pragma unroll
            for (int i=0;i<4;i++) cpa16(s0 + dofA[i], srcA[i] + ko);
            #pragma unroll
            for (int i=0;i<2;i++) cpa16(s0 + DN_BOFF_B + dofB[i], srcB[i] + ko);
        }
        CP_COMMIT();
    }

    // epilogue: atomicAdd weighted rows straight into out
    #pragma unroll
    for (int mt=0; mt<2; mt++){
        #pragma unroll
        for (int half=0; half<2; half++){
            int r = wm*32 + mt*16 + half*8 + g;
            if (m0 + r < Me){
                float wsc = g_slotW[base+m0+r];
                int   tok = g_slotTok[base+m0+r];
                float* orow = out + (size_t)tok*H_ + n0;
                #pragma unroll
                for (int nf=0; nf<4; nf++){
                    int col = wn*32 + nf*8 + 2*tg;
                    atomicAdd(&orow[col  ], acc[mt][nf][half*2  ]*wsc);
                    atomicAdd(&orow[col+1], acc[mt][nf][half*2+1]*wsc);
                }
            }
        }
    }
}

// ---------------- launch ----------------------------------------------------
extern "C" void kernel_launch(void* const* d_in, const int* in_sizes, int n_in,
                              void* d_out, int out_size){
    const float* RI = (const float*)d_in[0];
    const float* HS = (const float*)d_in[1];
    const float* WR = (const float*)d_in[2];
    const float* WG = (const float*)d_in[3];
    const float* WU = (const float*)d_in[4];
    const float* WD = (const float*)d_in[5];
    float* out    = (float*)d_out;
    float* logits = out + (size_t)T_*H_;

    cudaFuncSetAttribute(gateup_f16, cudaFuncAttributeMaxDynamicSharedMemorySize, GU_SMEM);
    cudaFuncSetAttribute(down_f16,   cudaFuncAttributeMaxDynamicSharedMemorySize, DN_SMEM);

    void* cntp; cudaGetSymbolAddress(&cntp, g_cnt);
    cudaMemsetAsync(out, 0, (size_t)T_*H_*sizeof(float));
    cudaMemsetAsync(cntp, 0, E_*sizeof(int));

    cvtrouter   <<<128+6400, 256>>>((const float4*)WG, (const float4*)WU,
                                    (const float4*)WD, (const float4*)HS,
                                    RI, WR, logits);
    scanscatter <<<1, 256>>>();
    gateup_f16  <<<dim3(F_/64, MAXTILES), 256, GU_SMEM>>>();
    down_f16    <<<dim3(H_/64, MAXTILES), 256, DN_SMEM>>>(out);
}

// round 10
// speedup vs baseline: 1.7656x; 1.0216x over previous
#include <cuda_runtime.h>
#include <cuda_fp16.h>
#include <cstdint>
#include <cstddef>

#define T_ 2048
#define H_ 1024
#define F_ 512
#define E_ 32
#define K_ 4
#define NSLOT (T_*K_)
#define SLOTPAD (NSLOT+128)
#define MAXTILES 96

#define RSTRIDE 144            // bytes per smem row (64 halves + 8 pad) — LDSM conflict-free
#define GU_STG_B  36864        // A 128*144 + G 64*144 + U 64*144
#define GU_GOFF_B 18432
#define GU_UOFF_B 27648
#define GU_SMEM   (3*GU_STG_B) // 110592
#define DN_STG_B  27648
#define DN_BOFF_B 18432
#define DN_SMEM   (4*DN_STG_B) // 110592 (4-stage)

// ---------------- scratch ----------------
__device__ int    g_cnt[E_];
__device__ int    g_off[E_+1];
__device__ int    g_sel[NSLOT];
__device__ float  g_wgt[NSLOT];
__device__ int    g_slotTok[SLOTPAD];
__device__ float  g_slotW[SLOTPAD];
__device__ int    g_tileE[MAXTILES];
__device__ int    g_tileM[MAXTILES];
__device__ __half g_WGh[(size_t)E_*F_*H_];
__device__ __half g_WUh[(size_t)E_*F_*H_];
__device__ __half g_WDh[(size_t)E_*H_*F_];
__device__ __half g_Xh [(size_t)T_*H_];
__device__ __half g_Hbuf16[(size_t)SLOTPAD*F_];

// ---------------- helpers ----------------
__device__ __forceinline__ uint32_t smem_u32(const void* p){
    uint32_t a; asm("{ .reg .u64 t; cvta.to.shared.u64 t, %1; cvt.u32.u64 %0, t; }" : "=r"(a) : "l"(p));
    return a;
}
__device__ __forceinline__ void cpa16(uint32_t dst, const void* src){
    asm volatile("cp.async.cg.shared.global [%0], [%1], 16;" :: "r"(dst), "l"(src) : "memory");
}
#define CP_COMMIT() asm volatile("cp.async.commit_group;" ::: "memory")
#define CP_WAIT1()  asm volatile("cp.async.wait_group 1;" ::: "memory")
#define CP_WAIT2()  asm volatile("cp.async.wait_group 2;" ::: "memory")

__device__ __forceinline__ void mma_f16(float* c, uint32_t a0,uint32_t a1,uint32_t a2,uint32_t a3,
                                        uint32_t b0,uint32_t b1){
    asm("mma.sync.aligned.m16n8k16.row.col.f32.f16.f16.f32 "
        "{%0,%1,%2,%3},{%4,%5,%6,%7},{%8,%9},{%0,%1,%2,%3};"
        : "+f"(c[0]),"+f"(c[1]),"+f"(c[2]),"+f"(c[3])
        : "r"(a0),"r"(a1),"r"(a2),"r"(a3),"r"(b0),"r"(b1));
}
__device__ __forceinline__ void ldsm4(uint32_t& r0,uint32_t& r1,uint32_t& r2,uint32_t& r3,
                                      uint32_t addr){
    asm volatile("ldmatrix.sync.aligned.m8n8.x4.shared.b16 {%0,%1,%2,%3}, [%4];"
        : "=r"(r0),"=r"(r1),"=r"(r2),"=r"(r3) : "r"(addr));
}

// ---------------- 1. fused convert(WG,WU,X) + router ------------------------
__global__ __launch_bounds__(256) void cvtrouter(const float4* __restrict__ wg,
                                                 const float4* __restrict__ wu,
                                                 const float4* __restrict__ hs,
                                                 const float* __restrict__ RI,
                                                 const float* __restrict__ WR,
                                                 float* __restrict__ logits){
    if (blockIdx.x < 128){
        int gid = blockIdx.x*256 + threadIdx.x;
        int warp = gid >> 5, lane = gid & 31;
        int t0 = warp*2;
        const float* xa = RI + (size_t)t0*H_;
        const float* xb = RI + (size_t)(t0+1)*H_;
        float4 ra[8], rb[8];
        #pragma unroll
        for (int j=0;j<8;j++){ ra[j] = *(const float4*)&xa[j*128 + lane*4];
                               rb[j] = *(const float4*)&xb[j*128 + lane*4]; }
        float l0 = 0.f, l1 = 0.f;
        for (int e=0;e<E_;e++){
            const float* w = WR + (size_t)e*H_;
            float s0=0.f, s1=0.f;
            #pragma unroll
            for (int j=0;j<8;j++){
                float4 wv = *(const float4*)&w[j*128 + lane*4];
                s0 += ra[j].x*wv.x + ra[j].y*wv.y + ra[j].z*wv.z + ra[j].w*wv.w;
                s1 += rb[j].x*wv.x + rb[j].y*wv.y + rb[j].z*wv.z + rb[j].w*wv.w;
            }
            #pragma unroll
            for (int off=16;off;off>>=1){
                s0 += __shfl_xor_sync(0xffffffffu, s0, off);
                s1 += __shfl_xor_sync(0xffffffffu, s1, off);
            }
            if (lane == e){ l0 = s0; l1 = s1; }
        }
        logits[(size_t)t0*E_ + lane]     = l0;
        logits[(size_t)(t0+1)*E_ + lane] = l1;
        #pragma unroll
        for (int tok=0; tok<2; tok++){
            int t = t0 + tok;
            float cur = (tok==0) ? l0 : l1;
            int idx = lane;
            float vsel[K_]; int isel[K_];
            #pragma unroll
            for (int k=0;k<K_;k++){
                float bv = cur; int bi = idx;
                #pragma unroll
                for (int off=16;off;off>>=1){
                    float ov = __shfl_xor_sync(0xffffffffu, bv, off);
                    int   oi = __shfl_xor_sync(0xffffffffu, bi, off);
                    if (ov > bv || (ov == bv && oi < bi)){ bv = ov; bi = oi; }
                }
                vsel[k]=bv; isel[k]=bi;
                if (idx == bi) cur = -__int_as_float(0x7f800000);
            }
            float mx = vsel[0], den = 0.f, w[K_];
            #pragma unroll
            for (int k=0;k<K_;k++){ w[k] = expf(vsel[k]-mx); den += w[k]; }
            if (lane < K_){
                g_sel[t*K_+lane] = isel[lane];
                g_wgt[t*K_+lane] = w[lane]/den;
                atomicAdd(&g_cnt[isel[lane]], 1);
            }
        }
        return;
    }
    const int NW = E_*F_*H_/8;
    const int NX = T_*H_/8;
    long c0 = ((long)(blockIdx.x-128)*256 + threadIdx.x)*4;
    if (c0 >= 2L*NW + NX) return;
    const float4* src; uint4* dst; long base;
    if      (c0 <    NW){ src=wg; dst=(uint4*)g_WGh; base=0; }
    else if (c0 < 2L*NW){ src=wu; dst=(uint4*)g_WUh; base=NW; }
    else                { src=hs; dst=(uint4*)g_Xh;  base=2L*NW; }
    long i = c0 - base;
    float4 a[8];
    #pragma unroll
    for (int j=0;j<8;j++) a[j] = src[2*i + j];
    #pragma unroll
    for (int j=0;j<4;j++){
        uint4 o;
        ((__half2*)&o)[0] = __floats2half2_rn(a[2*j].x,   a[2*j].y);
        ((__half2*)&o)[1] = __floats2half2_rn(a[2*j].z,   a[2*j].w);
        ((__half2*)&o)[2] = __floats2half2_rn(a[2*j+1].x, a[2*j+1].y);
        ((__half2*)&o)[3] = __floats2half2_rn(a[2*j+1].z, a[2*j+1].w);
        dst[i+j] = o;
    }
}

// ---------------- 2. scan + scatter + tile table (one block) ----------------
__global__ __launch_bounds__(256) void scanscatter(){
    __shared__ int soff[E_];
    __shared__ int spos[E_];
    int tid = threadIdx.x;
    if (tid < E_) spos[tid] = 0;
    if (tid == 0){
        int acc = 0;
        for (int e=0;e<E_;e++){ soff[e]=acc; g_off[e]=acc; acc += g_cnt[e]; }
        g_off[E_] = acc;
        int tt = 0;
        for (int e=0;e<E_;e++){
            int nt = (g_cnt[e]+127)>>7;
            for (int i=0;i<nt;i++){ g_tileE[tt]=e; g_tileM[tt]=i; tt++; }
        }
        for (; tt<MAXTILES; tt++) g_tileE[tt] = -1;
    }
    __syncthreads();
    for (int idx = tid; idx < NSLOT; idx += 256){
        int e = g_sel[idx];
        int slot = soff[e] + atomicAdd(&spos[e], 1);
        g_slotTok[slot] = idx >> 2;
        g_slotW[slot]   = g_wgt[idx];
    }
}

// ---------------- 3. gate+up GEMM (single-sync, 3-stage) + WD convert -------
__global__ __launch_bounds__(256,2) void gateup_f16(const float4* __restrict__ wd){
    extern __shared__ char smem[];
    int tile = blockIdx.y;
    if (tile >= MAXTILES){
        // WD fp32->fp16 convert, overlapped with GEMM blocks
        long cb = (long)(tile - MAXTILES)*8 + blockIdx.x;
        long i  = (cb*256 + threadIdx.x)*4;
        float4 a[8];
        #pragma unroll
        for (int j=0;j<8;j++) a[j] = wd[2*i + j];
        uint4* dst = (uint4*)g_WDh;
        #pragma unroll
        for (int j=0;j<4;j++){
            uint4 o;
            ((__half2*)&o)[0] = __floats2half2_rn(a[2*j].x,   a[2*j].y);
            ((__half2*)&o)[1] = __floats2half2_rn(a[2*j].z,   a[2*j].w);
            ((__half2*)&o)[2] = __floats2half2_rn(a[2*j+1].x, a[2*j+1].y);
            ((__half2*)&o)[3] = __floats2half2_rn(a[2*j+1].z, a[2*j+1].w);
            dst[i+j] = o;
        }
        return;
    }
    int e = g_tileE[tile];
    if (e < 0) return;
    int n0 = blockIdx.x*64;
    int m0 = g_tileM[tile]*128;
    int base = g_off[e];
    int Me   = g_off[e+1] - base;
    int tid = threadIdx.x, lane = tid&31, wid = tid>>5;
    uint32_t sb = smem_u32(smem);

    const __half* srcA[4]; uint32_t dofA[4];
    #pragma unroll
    for (int i=0;i<4;i++){
        int c = tid + i*256, row = c>>3, ch = c&7;
        int tok = g_slotTok[base + m0 + row];
        srcA[i] = g_Xh + (size_t)tok*H_ + ch*8;
        dofA[i] = (uint32_t)row*RSTRIDE + ch*16;
    }
    const __half* srcG[2]; const __half* srcU[2]; uint32_t dofB[2];
    #pragma unroll
    for (int i=0;i<2;i++){
        int c = tid + i*256, row = c>>3, ch = c&7;
        srcG[i] = g_WGh + (size_t)e*F_*H_ + (size_t)(n0+row)*H_ + ch*8;
        srcU[i] = g_WUh + (size_t)e*F_*H_ + (size_t)(n0+row)*H_ + ch*8;
        dofB[i] = (uint32_t)row*RSTRIDE + ch*16;
    }

    const int NK = H_/64;   // 16
    // prologue: 2 stages
    #pragma unroll
    for (int kt=0; kt<2; kt++){
        uint32_t s0 = sb + kt*GU_STG_B;
        #pragma unroll
        for (int i=0;i<4;i++) cpa16(s0 + dofA[i], srcA[i] + kt*64);
        #pragma unroll
        for (int i=0;i<2;i++){
            cpa16(s0 + GU_GOFF_B + dofB[i], srcG[i] + kt*64);
            cpa16(s0 + GU_UOFF_B + dofB[i], srcU[i] + kt*64);
        }
        CP_COMMIT();
    }

    int g = lane>>2, tg = lane&3;
    int wm = wid&3, wn = wid>>2;
    uint32_t aOff = (uint32_t)(wm*32 + (lane&7) + ((lane>>3)&1)*8)*RSTRIDE + ((lane>>4)&1)*16;
    uint32_t bOff = (uint32_t)(wn*32 + (lane&7) + ((lane>>4)&1)*8)*RSTRIDE + ((lane>>3)&1)*16;

    float accG[2][4][4] = {}; float accU[2][4][4] = {};

    for (int kt=0; kt<NK; kt++){
        CP_WAIT1();
        __syncthreads();
        // prefetch tile kt+2 into stage (kt+2)%3 (consumed at iter kt-1, safe after sync)
        if (kt+2 < NK){
            uint32_t s0 = sb + ((kt+2)%3)*GU_STG_B;
            int ko = (kt+2)*64;
            #pragma unroll
            for (int i=0;i<4;i++) cpa16(s0 + dofA[i], srcA[i] + ko);
            #pragma unroll
            for (int i=0;i<2;i++){
                cpa16(s0 + GU_GOFF_B + dofB[i], srcG[i] + ko);
                cpa16(s0 + GU_UOFF_B + dofB[i], srcU[i] + ko);
            }
        }
        CP_COMMIT();
        int s = kt - (kt/3)*3;
        uint32_t sA = sb + s*GU_STG_B;
        uint32_t sG = sA + GU_GOFF_B;
        uint32_t sU = sA + GU_UOFF_B;
        #pragma unroll
        for (int ks=0; ks<4; ks++){
            uint32_t a0[4], a1[4], bg[8], bu[8];
            ldsm4(a0[0],a0[1],a0[2],a0[3], sA + aOff + ks*32);
            ldsm4(a1[0],a1[1],a1[2],a1[3], sA + aOff + 16*RSTRIDE + ks*32);
            ldsm4(bg[0],bg[1],bg[2],bg[3], sG + bOff + ks*32);
            ldsm4(bg[4],bg[5],bg[6],bg[7], sG + bOff + 16*RSTRIDE + ks*32);
            ldsm4(bu[0],bu[1],bu[2],bu[3], sU + bOff + ks*32);
            ldsm4(bu[4],bu[5],bu[6],bu[7], sU + bOff + 16*RSTRIDE + ks*32);
            #pragma unroll
            for (int nf=0; nf<4; nf++){
                mma_f16(accG[0][nf], a0[0],a0[1],a0[2],a0[3], bg[nf*2],bg[nf*2+1]);
                mma_f16(accG[1][nf], a1[0],a1[1],a1[2],a1[3], bg[nf*2],bg[nf*2+1]);
                mma_f16(accU[0][nf], a0[0],a0[1],a0[2],a0[3], bu[nf*2],bu[nf*2+1]);
                mma_f16(accU[1][nf], a1[0],a1[1],a1[2],a1[3], bu[nf*2],bu[nf*2+1]);
            }
        }
    }

    #pragma unroll
    for (int mt=0; mt<2; mt++){
        #pragma unroll
        for (int half=0; half<2; half++){
            int r = wm*32 + mt*16 + half*8 + g;
            if (m0 + r < Me){
                size_t ob = (size_t)(base+m0+r)*F_ + n0;
                #pragma unroll
                for (int nf=0; nf<4; nf++){
                    int col = wn*32 + nf*8 + 2*tg;
                    float h0 = fmaxf(accG[mt][nf][half*2  ],0.f)*accU[mt][nf][half*2  ];
                    float h1 = fmaxf(accG[mt][nf][half*2+1],0.f)*accU[mt][nf][half*2+1];
                    *(__half2*)&g_Hbuf16[ob + col] = __floats2half2_rn(h0,h1);
                }
            }
        }
    }
}

// ---------------- 4. down GEMM (single-sync, 4-stage), atomic epilogue ------
__global__ __launch_bounds__(256,2) void down_f16(float* __restrict__ out){
    extern __shared__ char smem[];
    int tile = blockIdx.y;
    int e = g_tileE[tile];
    if (e < 0) return;
    int n0 = blockIdx.x*64;
    int m0 = g_tileM[tile]*128;
    int base = g_off[e];
    int Me   = g_off[e+1] - base;
    int tid = threadIdx.x, lane = tid&31, wid = tid>>5;
    uint32_t sb = smem_u32(smem);

    const __half* srcA[4]; uint32_t dofA[4];
    #pragma unroll
    for (int i=0;i<4;i++){
        int c = tid + i*256, row = c>>3, ch = c&7;
        srcA[i] = g_Hbuf16 + (size_t)(base+m0+row)*F_ + ch*8;
        dofA[i] = (uint32_t)row*RSTRIDE + ch*16;
    }
    const __half* srcB[2]; uint32_t dofB[2];
    #pragma unroll
    for (int i=0;i<2;i++){
        int c = tid + i*256, row = c>>3, ch = c&7;
        srcB[i] = g_WDh + (size_t)e*H_*F_ + (size_t)(n0+row)*F_ + ch*8;
        dofB[i] = (uint32_t)row*RSTRIDE + ch*16;
    }

    const int NK = F_/64;   // 8
    // prologue: 3 stages
    #pragma unroll
    for (int kt=0; kt<3; kt++){
        uint32_t s0 = sb + kt*DN_STG_B;
        #pragma unroll
        for (int i=0;i<4;i++) cpa16(s0 + dofA[i], srcA[i] + kt*64);
        #pragma unroll
        for (int i=0;i<2;i++) cpa16(s0 + DN_BOFF_B + dofB[i], srcB[i] + kt*64);
        CP_COMMIT();
    }

    int g = lane>>2, tg = lane&3;
    int wm = wid&3, wn = wid>>2;
    uint32_t aOff = (uint32_t)(wm*32 + (lane&7) + ((lane>>3)&1)*8)*RSTRIDE + ((lane>>4)&1)*16;
    uint32_t bOff = (uint32_t)(wn*32 + (lane&7) + ((lane>>4)&1)*8)*RSTRIDE + ((lane>>3)&1)*16;

    float acc[2][4][4] = {};

    for (int kt=0; kt<NK; kt++){
        CP_WAIT2();
        __syncthreads();
        if (kt+3 < NK){
            uint32_t s0 = sb + ((kt+3)&3)*DN_STG_B;
            int ko = (kt+3)*64;
            #pragma unroll
            for (int i=0;i<4;i++) cpa16(s0 + dofA[i], srcA[i] + ko);
            #pragma unroll
            for (int i=0;i<2;i++) cpa16(s0 + DN_BOFF_B + dofB[i], srcB[i] + ko);
        }
        CP_COMMIT();
        int s = kt & 3;
        uint32_t sA = sb + s*DN_STG_B;
        uint32_t sB = sA + DN_BOFF_B;
        #pragma unroll
        for (int ks=0; ks<4; ks++){
            uint32_t a0[4], a1[4], bb[8];
            ldsm4(a0[0],a0[1],a0[2],a0[3], sA + aOff + ks*32);
            ldsm4(a1[0],a1[1],a1[2],a1[3], sA + aOff + 16*RSTRIDE + ks*32);
            ldsm4(bb[0],bb[1],bb[2],bb[3], sB + bOff + ks*32);
            ldsm4(bb[4],bb[5],bb[6],bb[7], sB + bOff + 16*RSTRIDE + ks*32);
            #pragma unroll
            for (int nf=0; nf<4; nf++){
                mma_f16(acc[0][nf], a0[0],a0[1],a0[2],a0[3], bb[nf*2],bb[nf*2+1]);
                mma_f16(acc[1][nf], a1[0],a1[1],a1[2],a1[3], bb[nf*2],bb[nf*2+1]);
            }
        }
    }

    #pragma unroll
    for (int mt=0; mt<2; mt++){
        #pragma unroll
        for (int half=0; half<2; half++){
            int r = wm*32 + mt*16 + half*8 + g;
            if (m0 + r < Me){
                float wsc = g_slotW[base+m0+r];
                int   tok = g_slotTok[base+m0+r];
                float* orow = out + (size_t)tok*H_ + n0;
                #pragma unroll
                for (int nf=0; nf<4; nf++){
                    int col = wn*32 + nf*8 + 2*tg;
                    atomicAdd(&orow[col  ], acc[mt][nf][half*2  ]*wsc);
                    atomicAdd(&orow[col+1], acc[mt][nf][half*2+1]*wsc);
                }
            }
        }
    }
}

// ---------------- launch ----------------------------------------------------
extern "C" void kernel_launch(void* const* d_in, const int* in_sizes, int n_in,
                              void* d_out, int out_size){
    const float* RI = (const float*)d_in[0];
    const float* HS = (const float*)d_in[1];
    const float* WR = (const float*)d_in[2];
    const float* WG = (const float*)d_in[3];
    const float* WU = (const float*)d_in[4];
    const float* WD = (const float*)d_in[5];
    float* out    = (float*)d_out;
    float* logits = out + (size_t)T_*H_;

    cudaFuncSetAttribute(gateup_f16, cudaFuncAttributeMaxDynamicSharedMemorySize, GU_SMEM);
    cudaFuncSetAttribute(down_f16,   cudaFuncAttributeMaxDynamicSharedMemorySize, DN_SMEM);

    void* cntp; cudaGetSymbolAddress(&cntp, g_cnt);
    cudaMemsetAsync(out, 0, (size_t)T_*H_*sizeof(float));
    cudaMemsetAsync(cntp, 0, E_*sizeof(int));

    // cvtrouter: 128 router blocks + (2*NW + NX)/1024 = 4352 convert blocks
    cvtrouter   <<<128+4352, 256>>>((const float4*)WG, (const float4*)WU,
                                    (const float4*)HS, RI, WR, logits);
    scanscatter <<<1, 256>>>();
    // gateup: 8 x (96 GEMM tiles + 256 WD-convert blocks)
    gateup_f16  <<<dim3(F_/64, MAXTILES+256), 256, GU_SMEM>>>((const float4*)WD);
    down_f16    <<<dim3(H_/64, MAXTILES), 256, DN_SMEM>>>(out);
}